// round 3
// baseline (speedup 1.0000x reference)
#include <cuda_runtime.h>

#define Bq 8
#define Nq 2048
#define Kq 32
#define Dq 64
#define C1q 64
#define C2q 128
#define GROUPS (Bq*Nq)        /* 16384 */
#define ROWS (GROUPS*Kq)      /* 524288 */
#define RAD2 (0.15f*0.15f)
#define EPSq 1e-5f

typedef unsigned long long u64;

// ---------------- scratch (device globals: allocation-free rule) ----------------
__device__ int   g_idx[GROUPS*Kq];                    // 2 MB
__device__ float g_h1[(size_t)ROWS*C1q];              // 134 MB
__device__ float g_h2[(size_t)ROWS*C2q];              // 268 MB
__device__ float g_stats1[2*C1q];                     // sum | sumsq
__device__ float g_stats2[2*C2q];
__device__ float g_sc1[2*C1q];                        // scale | shift
__device__ float g_sc2[2*C2q];

// ---------------- packed fp32x2 helpers ----------------
__device__ __forceinline__ void ffma2(u64 &d, u64 a, u64 b) {
    asm("fma.rn.f32x2 %0, %1, %2, %0;" : "+l"(d) : "l"(a), "l"(b));
}
__device__ __forceinline__ u64 pack2(float v) {
    u64 r; asm("mov.b64 %0, {%1, %1};" : "=l"(r) : "f"(v)); return r;
}
__device__ __forceinline__ float2 unpack2(u64 v) {
    float2 f; asm("mov.b64 {%0, %1}, %2;" : "=f"(f.x), "=f"(f.y) : "l"(v)); return f;
}

// ---------------- kernel 0: zero stats accumulators (per-replay determinism) ----------------
__global__ void zero_kernel() {
    int t = threadIdx.x;
    if (t < 2*C1q) g_stats1[t] = 0.f;
    if (t < 2*C2q) g_stats2[t] = 0.f;
}

// ---------------- kernel 1: ball query ----------------
// One warp per center; first-K-in-index-order via ballot; pad with first index.
__global__ __launch_bounds__(256) void bq_kernel(const float* __restrict__ pos) {
    __shared__ float s_p[Nq*3];
    __shared__ float s_sq[Nq];
    __shared__ int   s_idx[8][Kq];
    int b = blockIdx.y;
    const float* pb = pos + (size_t)b*Nq*3;
    for (int i = threadIdx.x; i < Nq*3; i += blockDim.x) s_p[i] = pb[i];
    __syncthreads();
    for (int i = threadIdx.x; i < Nq; i += blockDim.x) {
        float x = s_p[3*i], y = s_p[3*i+1], z = s_p[3*i+2];
        s_sq[i] = x*x + y*y + z*z;
    }
    __syncthreads();
    int w = threadIdx.x >> 5, lane = threadIdx.x & 31;
    for (int it = 0; it < 8; it++) {
        int j = blockIdx.x*64 + it*8 + w;
        float cx = s_p[3*j], cy = s_p[3*j+1], cz = s_p[3*j+2];
        float csq = s_sq[j];
        int cnt = 0;
        for (int base = 0; base < Nq; base += 32) {
            int m = base + lane;
            // mirror JAX: |a|^2 + |b|^2 - 2 a.b ; inside iff !(sq > r^2)
            float d = csq + s_sq[m]
                    - 2.0f*(cx*s_p[3*m] + cy*s_p[3*m+1] + cz*s_p[3*m+2]);
            bool v = !(d > RAD2);
            unsigned msk = __ballot_sync(0xffffffffu, v);
            int p = cnt + __popc(msk & ((1u << lane) - 1u));
            if (v && p < Kq) s_idx[w][p] = m;
            cnt += __popc(msk);
            if (cnt >= Kq) break;
        }
        __syncwarp();
        int first = s_idx[w][0];                 // cnt >= 1 always (self, dist 0)
        int nvalid = cnt < Kq ? cnt : Kq;
        int val = (lane < nvalid) ? s_idx[w][lane] : first;
        g_idx[((size_t)b*Nq + j)*Kq + lane] = val;
        __syncwarp();
    }
}

// ---------------- kernel 2: GEMM1 (x[32,67] @ W1[67,64]) + stats1 ----------------
#define SX1 69   /* odd pad -> conflict-free column reads */
__global__ __launch_bounds__(128) void gemm1_kernel(const float* __restrict__ pos,
                                                    const float* __restrict__ feat,
                                                    const float* __restrict__ W1) {
    __shared__ float s_w[67*64];
    __shared__ float s_x[32*SX1];
    __shared__ float s_o[32*65];
    __shared__ int   s_nb[32];
    int t = threadIdx.x;
    for (int i = t; i < 67*64; i += 128) s_w[i] = W1[i];
    int r = t & 31, cg = t >> 5;
    int c0 = cg * 16;
    float sum[16], sq[16];
#pragma unroll
    for (int j = 0; j < 16; j++) { sum[j] = 0.f; sq[j] = 0.f; }

    for (int g = 0; g < 8; g++) {
        int gg = blockIdx.x*8 + g;
        int b = gg >> 11, n = gg & 2047;
        size_t rowbase = (size_t)gg * 32;
        if (t < 32) {
            int nb = g_idx[rowbase + t];
            s_nb[t] = nb;
            const float* pc = pos + ((size_t)b*Nq + n)*3;
            const float* pn = pos + ((size_t)b*Nq + nb)*3;
            s_x[t*SX1 + 0] = pn[0] - pc[0];
            s_x[t*SX1 + 1] = pn[1] - pc[1];
            s_x[t*SX1 + 2] = pn[2] - pc[2];
        }
        __syncthreads();
        for (int i = t; i < 32*64; i += 128) {
            int rr = i >> 6, c = i & 63;
            int nb = s_nb[rr];
            s_x[rr*SX1 + 3 + c] = feat[((size_t)b*Nq + nb)*64 + c];
        }
        __syncthreads();

        u64 acc[8];
#pragma unroll
        for (int j = 0; j < 8; j++) acc[j] = 0ull;
        const float* xr = s_x + r*SX1;
        for (int k = 0; k < 67; k++) {
            u64 xx = pack2(xr[k]);
            const ulonglong2* wp = (const ulonglong2*)(s_w + k*64 + c0);
            ulonglong2 w0 = wp[0], w1 = wp[1], w2 = wp[2], w3 = wp[3];
            ffma2(acc[0], xx, w0.x); ffma2(acc[1], xx, w0.y);
            ffma2(acc[2], xx, w1.x); ffma2(acc[3], xx, w1.y);
            ffma2(acc[4], xx, w2.x); ffma2(acc[5], xx, w2.y);
            ffma2(acc[6], xx, w3.x); ffma2(acc[7], xx, w3.y);
        }
#pragma unroll
        for (int j = 0; j < 8; j++) {
            float2 v = unpack2(acc[j]);
            sum[2*j]   += v.x;  sq[2*j]   += v.x*v.x;
            sum[2*j+1] += v.y;  sq[2*j+1] += v.y*v.y;
            s_o[r*65 + c0 + 2*j]     = v.x;   // pad 65: conflict-free scalar STS
            s_o[r*65 + c0 + 2*j + 1] = v.y;
        }
        __syncthreads();
        float* dst = g_h1 + rowbase*64;
        for (int i = t; i < 2048; i += 128)
            dst[i] = s_o[(i >> 6)*65 + (i & 63)];
        __syncthreads();
    }
    // warp-reduce stats across rows, lane 0 atomics
#pragma unroll
    for (int j = 0; j < 16; j++) {
        for (int off = 16; off; off >>= 1) {
            sum[j] += __shfl_xor_sync(0xffffffffu, sum[j], off);
            sq[j]  += __shfl_xor_sync(0xffffffffu, sq[j],  off);
        }
    }
    if (r == 0) {
#pragma unroll
        for (int j = 0; j < 16; j++) {
            atomicAdd(&g_stats1[c0 + j],        sum[j]);
            atomicAdd(&g_stats1[C1q + c0 + j],  sq[j]);
        }
    }
}

// ---------------- kernel 3/5: finalize BN stats -> scale/shift ----------------
__global__ void fin1_kernel(const float* __restrict__ gamma, const float* __restrict__ beta) {
    int c = threadIdx.x;
    float inv = 1.0f / (float)ROWS;
    float mean = g_stats1[c] * inv;
    float var  = g_stats1[C1q + c] * inv - mean*mean;
    float sc   = gamma[c] * rsqrtf(var + EPSq);
    g_sc1[c] = sc;
    g_sc1[C1q + c] = beta[c] - mean*sc;
}
__global__ void fin2_kernel(const float* __restrict__ gamma, const float* __restrict__ beta) {
    int c = threadIdx.x;
    float inv = 1.0f / (float)ROWS;
    float mean = g_stats2[c] * inv;
    float var  = g_stats2[C2q + c] * inv - mean*mean;
    float sc   = gamma[c] * rsqrtf(var + EPSq);
    g_sc2[c] = sc;
    g_sc2[C2q + c] = beta[c] - mean*sc;
}

// ---------------- kernel 4: normalize+ReLU, GEMM2 (h1n[32,64] @ W2[64,128]) + stats2 ----------------
__global__ __launch_bounds__(256) void gemm2_kernel(const float* __restrict__ W2) {
    extern __shared__ float sm[];
    float* s_w = sm;                 // 64*128
    float* s_h = s_w + 64*128;       // 32*65
    float* s_o = s_h + 32*65;        // 32*129
    int t = threadIdx.x;
    for (int i = t; i < 64*128; i += 256) s_w[i] = W2[i];
    int r = t & 31, cg = t >> 5;
    int c0 = cg * 16;
    float sum[16], sq[16];
#pragma unroll
    for (int j = 0; j < 16; j++) { sum[j] = 0.f; sq[j] = 0.f; }

    for (int g = 0; g < 8; g++) {
        int gg = blockIdx.x*8 + g;
        size_t rowbase = (size_t)gg * 32;
        const float* src = g_h1 + rowbase*64;
        for (int i = t; i < 2048; i += 256) {
            int rr = i >> 6, k = i & 63;
            float v = src[i];
            v = fmaf(v, g_sc1[k], g_sc1[C1q + k]);
            s_h[rr*65 + k] = fmaxf(v, 0.f);
        }
        __syncthreads();

        u64 acc[8];
#pragma unroll
        for (int j = 0; j < 8; j++) acc[j] = 0ull;
        const float* xr = s_h + r*65;
        for (int k = 0; k < 64; k++) {
            u64 xx = pack2(xr[k]);
            const ulonglong2* wp = (const ulonglong2*)(s_w + k*128 + c0);
            ulonglong2 w0 = wp[0], w1 = wp[1], w2 = wp[2], w3 = wp[3];
            ffma2(acc[0], xx, w0.x); ffma2(acc[1], xx, w0.y);
            ffma2(acc[2], xx, w1.x); ffma2(acc[3], xx, w1.y);
            ffma2(acc[4], xx, w2.x); ffma2(acc[5], xx, w2.y);
            ffma2(acc[6], xx, w3.x); ffma2(acc[7], xx, w3.y);
        }
#pragma unroll
        for (int j = 0; j < 8; j++) {
            float2 v = unpack2(acc[j]);
            sum[2*j]   += v.x;  sq[2*j]   += v.x*v.x;
            sum[2*j+1] += v.y;  sq[2*j+1] += v.y*v.y;
            s_o[r*129 + c0 + 2*j]     = v.x;
            s_o[r*129 + c0 + 2*j + 1] = v.y;
        }
        __syncthreads();
        float* dst = g_h2 + rowbase*128;
        for (int i = t; i < 4096; i += 256)
            dst[i] = s_o[(i >> 7)*129 + (i & 127)];
        __syncthreads();
    }
#pragma unroll
    for (int j = 0; j < 16; j++) {
        for (int off = 16; off; off >>= 1) {
            sum[j] += __shfl_xor_sync(0xffffffffu, sum[j], off);
            sq[j]  += __shfl_xor_sync(0xffffffffu, sq[j],  off);
        }
    }
    if (r == 0) {
#pragma unroll
        for (int j = 0; j < 16; j++) {
            atomicAdd(&g_stats2[c0 + j],        sum[j]);
            atomicAdd(&g_stats2[C2q + c0 + j],  sq[j]);
        }
    }
}

// ---------------- kernel 6: normalize+ReLU + max over K ----------------
__global__ __launch_bounds__(128) void maxpool_kernel(float* __restrict__ out) {
    int t = threadIdx.x;
    float scale = g_sc2[t];
    float shift = g_sc2[C2q + t];
    for (int g = 0; g < 8; g++) {
        size_t gg = (size_t)blockIdx.x*8 + g;
        const float* hp = g_h2 + gg*32*128;
        float m = -3.402823466e38f;
#pragma unroll 8
        for (int rr = 0; rr < 32; rr++)
            m = fmaxf(m, fmaf(hp[rr*128 + t], scale, shift));
        out[gg*128 + t] = fmaxf(m, 0.f);
    }
}

static const int GEMM2_SMEM = (64*128 + 32*65 + 32*129) * (int)sizeof(float);  // 57600 B

extern "C" void kernel_launch(void* const* d_in, const int* in_sizes, int n_in,
                              void* d_out, int out_size) {
    (void)in_sizes; (void)n_in; (void)out_size;
    const float* pos  = (const float*)d_in[0];
    const float* feat = (const float*)d_in[1];
    const float* W1   = (const float*)d_in[2];
    const float* g1   = (const float*)d_in[3];
    const float* b1   = (const float*)d_in[4];
    const float* W2   = (const float*)d_in[5];
    const float* g2   = (const float*)d_in[6];
    const float* b2   = (const float*)d_in[7];
    float* out = (float*)d_out;

    cudaFuncSetAttribute(gemm2_kernel, cudaFuncAttributeMaxDynamicSharedMemorySize, GEMM2_SMEM);

    // position passthrough (first output of the tuple)
    cudaMemcpyAsync(out, pos, (size_t)Bq*Nq*3*sizeof(float), cudaMemcpyDeviceToDevice, 0);

    zero_kernel<<<1, 256>>>();
    bq_kernel<<<dim3(Nq/64, Bq), 256>>>(pos);
    gemm1_kernel<<<GROUPS/8, 128>>>(pos, feat, W1);
    fin1_kernel<<<1, C1q>>>(g1, b1);
    gemm2_kernel<<<GROUPS/8, 256, GEMM2_SMEM>>>(W2);
    fin2_kernel<<<1, C2q>>>(g2, b2);
    maxpool_kernel<<<GROUPS/8, 128>>>(out + (size_t)Bq*Nq*3);
}

// round 5
// speedup vs baseline: 1.3568x; 1.3568x over previous
#include <cuda_runtime.h>

#define Bq 8
#define Nq 2048
#define Kq 32
#define Dq 64
#define C1q 64
#define C2q 128
#define GROUPS (Bq*Nq)        /* 16384 */
#define ROWS (GROUPS*Kq)      /* 524288 */
#define RAD2 (0.15f*0.15f)
#define EPSq 1e-5f
#define XP 68                 /* x-tile row stride: 68 mod 32 == 4 -> conflict-free LDS.128 */

typedef unsigned long long u64;

// ---------------- scratch (device globals: allocation-free rule) ----------------
__device__ int   g_idx[GROUPS*Kq];                    // 2 MB
__device__ float g_h1[(size_t)ROWS*C1q];              // 134 MB
__device__ float g_gmax[(size_t)GROUPS*C2q];          // 8 MB  (per-group max of raw h2)
__device__ float g_gmin[(size_t)GROUPS*C2q];          // 8 MB  (per-group min, for scale<0 safety)
__device__ float g_stats1[2*C1q];                     // sum | sumsq
__device__ float g_stats2[2*C2q];
__device__ float g_sc1[2*C1q];                        // scale | shift
__device__ float g_sc2[2*C2q];

// ---------------- packed fp32x2 helpers ----------------
__device__ __forceinline__ void ffma2(u64 &d, u64 a, u64 b) {
    asm("fma.rn.f32x2 %0, %1, %2, %0;" : "+l"(d) : "l"(a), "l"(b));
}
__device__ __forceinline__ u64 pack2(float v) {
    u64 r; asm("mov.b64 %0, {%1, %1};" : "=l"(r) : "f"(v)); return r;
}
__device__ __forceinline__ float2 unpack2(u64 v) {
    float2 f; asm("mov.b64 {%0, %1}, %2;" : "=f"(f.x), "=f"(f.y) : "l"(v)); return f;
}

// ---------------- kernel 0: zero stats accumulators ----------------
__global__ void zero_kernel() {
    int t = threadIdx.x;
    if (t < 2*C1q) g_stats1[t] = 0.f;
    if (t < 2*C2q) g_stats2[t] = 0.f;
}

// ---------------- kernel 1: ball query (one warp per center) ----------------
__global__ __launch_bounds__(256) void bq_kernel(const float* __restrict__ pos) {
    __shared__ float s_p[Nq*3];
    __shared__ float s_sq[Nq];
    __shared__ int   s_idx[8][Kq];
    int b = blockIdx.y;
    const float* pb = pos + (size_t)b*Nq*3;
    for (int i = threadIdx.x; i < Nq*3; i += blockDim.x) s_p[i] = pb[i];
    __syncthreads();
    for (int i = threadIdx.x; i < Nq; i += blockDim.x) {
        float x = s_p[3*i], y = s_p[3*i+1], z = s_p[3*i+2];
        s_sq[i] = x*x + y*y + z*z;
    }
    __syncthreads();
    int w = threadIdx.x >> 5, lane = threadIdx.x & 31;
    for (int it = 0; it < 8; it++) {
        int j = blockIdx.x*64 + it*8 + w;
        float cx = s_p[3*j], cy = s_p[3*j+1], cz = s_p[3*j+2];
        float csq = s_sq[j];
        int cnt = 0;
        for (int base = 0; base < Nq; base += 32) {
            int m = base + lane;
            float d = csq + s_sq[m]
                    - 2.0f*(cx*s_p[3*m] + cy*s_p[3*m+1] + cz*s_p[3*m+2]);
            bool v = !(d > RAD2);
            unsigned msk = __ballot_sync(0xffffffffu, v);
            int p = cnt + __popc(msk & ((1u << lane) - 1u));
            if (v && p < Kq) s_idx[w][p] = m;
            cnt += __popc(msk);
            if (cnt >= Kq) break;
        }
        __syncwarp();
        int first = s_idx[w][0];
        int nvalid = cnt < Kq ? cnt : Kq;
        int val = (lane < nvalid) ? s_idx[w][lane] : first;
        g_idx[((size_t)b*Nq + j)*Kq + lane] = val;
        __syncwarp();
    }
}

// ---------------- kernel 2: GEMM1 (x[32,67] @ W1[67,64]) + stats1, direct STG of h1 ----------------
// 256 threads, 4 groups per iteration, 8 iterations -> 32 groups/block.
// Per group: 64 threads, each computes rows {r0, r0+16} x 16 cols.
__global__ __launch_bounds__(256) void gemm1_kernel(const float* __restrict__ pos,
                                                    const float* __restrict__ feat,
                                                    const float* __restrict__ W1) {
    extern __shared__ float sm[];
    float* s_w = sm;                       // 68*64  (row 67 zero-padded)
    float* s_x = s_w + 68*64;              // 4 * 32 * XP
    int*   s_nb = (int*)(s_x + 4*32*XP);   // 4*32
    int t = threadIdx.x;
    for (int i = t; i < 68*64; i += 256) s_w[i] = (i < 67*64) ? W1[i] : 0.f;
    int u = t & 63, ga = t >> 6;
    int r0 = u & 15, c0 = (u >> 4) * 16;
    float sum[16], sq[16];
#pragma unroll
    for (int j = 0; j < 16; j++) { sum[j] = 0.f; sq[j] = 0.f; }

    for (int it = 0; it < 8; it++) {
        int gg0 = blockIdx.x*32 + it*4;
        __syncthreads();                   // s_x reuse guard (and s_w on iter 0)
        if (t < 128) {
            int g2 = t >> 5, row = t & 31;
            int gg = gg0 + g2;
            int b = gg >> 11, n = gg & 2047;
            int nb = g_idx[(size_t)gg*32 + row];
            s_nb[g2*32 + row] = nb;
            const float* pc = pos + ((size_t)b*Nq + n)*3;
            const float* pn = pos + ((size_t)b*Nq + nb)*3;
            float* xr = s_x + (g2*32 + row)*XP;
            xr[0] = pn[0] - pc[0];
            xr[1] = pn[1] - pc[1];
            xr[2] = pn[2] - pc[2];
            xr[67] = 0.f;                  // pad col (paired with zero w row 67)
        }
        __syncthreads();
#pragma unroll
        for (int j = 0; j < 8; j++) {      // 2048 float4 of feat
            int i = t + 256*j;
            int g2 = i >> 9, rr = (i >> 4) & 31, c4 = i & 15;
            int gg = gg0 + g2;
            int b = gg >> 11;
            int nb = s_nb[g2*32 + rr];
            float4 v = *(const float4*)(feat + (((size_t)b*Nq + nb)*64 + c4*4));
            float* xr = s_x + (g2*32 + rr)*XP + 3 + c4*4;
            xr[0] = v.x; xr[1] = v.y; xr[2] = v.z; xr[3] = v.w;
        }
        __syncthreads();

        u64 acc[16];
#pragma unroll
        for (int j = 0; j < 16; j++) acc[j] = 0ull;
        const float* xa = s_x + (ga*32 + r0)*XP;
        const float* xb = xa + 16*XP;
#pragma unroll 2
        for (int k4 = 0; k4 < 68; k4 += 4) {
            float4 va = *(const float4*)(xa + k4);
            float4 vb = *(const float4*)(xb + k4);
#pragma unroll
            for (int kk = 0; kk < 4; kk++) {
                u64 x0 = pack2((&va.x)[kk]);
                u64 x1 = pack2((&vb.x)[kk]);
                const ulonglong2* wp = (const ulonglong2*)(s_w + (k4+kk)*64 + c0);
                ulonglong2 w0 = wp[0], w1 = wp[1], w2 = wp[2], w3 = wp[3];
                ffma2(acc[0], x0, w0.x); ffma2(acc[1], x0, w0.y);
                ffma2(acc[2], x0, w1.x); ffma2(acc[3], x0, w1.y);
                ffma2(acc[4], x0, w2.x); ffma2(acc[5], x0, w2.y);
                ffma2(acc[6], x0, w3.x); ffma2(acc[7], x0, w3.y);
                ffma2(acc[8],  x1, w0.x); ffma2(acc[9],  x1, w0.y);
                ffma2(acc[10], x1, w1.x); ffma2(acc[11], x1, w1.y);
                ffma2(acc[12], x1, w2.x); ffma2(acc[13], x1, w2.y);
                ffma2(acc[14], x1, w3.x); ffma2(acc[15], x1, w3.y);
            }
        }
        // epilogue: stats + direct float4 STG of h1
        int gg = gg0 + ga;
        float* d0 = g_h1 + ((size_t)gg*32 + r0)*64 + c0;
        float* d1 = d0 + (size_t)16*64;
#pragma unroll
        for (int j = 0; j < 4; j++) {
            float2 a0 = unpack2(acc[2*j]),   a1 = unpack2(acc[2*j+1]);
            float2 b0 = unpack2(acc[8+2*j]), b1 = unpack2(acc[9+2*j]);
            sum[4*j]   += a0.x + b0.x;  sq[4*j]   += a0.x*a0.x + b0.x*b0.x;
            sum[4*j+1] += a0.y + b0.y;  sq[4*j+1] += a0.y*a0.y + b0.y*b0.y;
            sum[4*j+2] += a1.x + b1.x;  sq[4*j+2] += a1.x*a1.x + b1.x*b1.x;
            sum[4*j+3] += a1.y + b1.y;  sq[4*j+3] += a1.y*a1.y + b1.y*b1.y;
            *(float4*)(d0 + 4*j) = make_float4(a0.x, a0.y, a1.x, a1.y);
            *(float4*)(d1 + 4*j) = make_float4(b0.x, b0.y, b1.x, b1.y);
        }
    }
    // width-16 shuffle reduce (lanes 0-15 / 16-31 reduce independently)
#pragma unroll
    for (int j = 0; j < 16; j++) {
        for (int off = 8; off; off >>= 1) {
            sum[j] += __shfl_xor_sync(0xffffffffu, sum[j], off);
            sq[j]  += __shfl_xor_sync(0xffffffffu, sq[j],  off);
        }
    }
    if ((u & 15) == 0) {
#pragma unroll
        for (int j = 0; j < 16; j++) {
            atomicAdd(&g_stats1[c0 + j],       sum[j]);
            atomicAdd(&g_stats1[C1q + c0 + j], sq[j]);
        }
    }
}

// ---------------- kernel 3/5: finalize BN stats -> scale/shift ----------------
__global__ void fin1_kernel(const float* __restrict__ gamma, const float* __restrict__ beta) {
    int c = threadIdx.x;
    float inv = 1.0f / (float)ROWS;
    float mean = g_stats1[c] * inv;
    float var  = g_stats1[C1q + c] * inv - mean*mean;
    float sc   = gamma[c] * rsqrtf(var + EPSq);
    g_sc1[c] = sc;
    g_sc1[C1q + c] = beta[c] - mean*sc;
}
__global__ void fin2_kernel(const float* __restrict__ gamma, const float* __restrict__ beta) {
    int c = threadIdx.x;
    float inv = 1.0f / (float)ROWS;
    float mean = g_stats2[c] * inv;
    float var  = g_stats2[C2q + c] * inv - mean*mean;
    float sc   = gamma[c] * rsqrtf(var + EPSq);
    g_sc2[c] = sc;
    g_sc2[C2q + c] = beta[c] - mean*sc;
}

// ---------------- kernel 4: normalize+ReLU, GEMM2 + stats2 + in-register group max/min ----------------
// 256 threads, 2 groups per iteration, 8 iterations -> 16 groups/block. No h2 materialization.
__global__ __launch_bounds__(256) void gemm2_kernel(const float* __restrict__ W2) {
    extern __shared__ float sm[];
    float* s_w  = sm;                 // 64*128
    float* s_h  = s_w + 64*128;       // 2 * 32 * XP
    float* s_sc = s_h + 2*32*XP;      // 128
    int t = threadIdx.x;
    for (int i = t; i < 64*128; i += 256) s_w[i] = W2[i];
    if (t < 128) s_sc[t] = g_sc1[t];
    int u = t & 127, ga = t >> 7;
    int r0 = u & 15, c0 = (u >> 4) * 16;
    float sum[16], sq[16];
#pragma unroll
    for (int j = 0; j < 16; j++) { sum[j] = 0.f; sq[j] = 0.f; }

    for (int it = 0; it < 8; it++) {
        int gg0 = blockIdx.x*16 + it*2;
        __syncthreads();
#pragma unroll
        for (int j = 0; j < 4; j++) {     // 1024 float4 of h1, normalize+relu into s_h
            int i = t + 256*j;
            int g2 = i >> 9, rr = (i >> 4) & 31, c4 = i & 15;
            float4 v = *(const float4*)(g_h1 + ((size_t)(gg0+g2)*32 + rr)*64 + c4*4);
            int c = c4*4;
            float* xr = s_h + (g2*32 + rr)*XP + c;
            xr[0] = fmaxf(fmaf(v.x, s_sc[c+0], s_sc[64+c+0]), 0.f);
            xr[1] = fmaxf(fmaf(v.y, s_sc[c+1], s_sc[64+c+1]), 0.f);
            xr[2] = fmaxf(fmaf(v.z, s_sc[c+2], s_sc[64+c+2]), 0.f);
            xr[3] = fmaxf(fmaf(v.w, s_sc[c+3], s_sc[64+c+3]), 0.f);
        }
        __syncthreads();

        u64 acc[16];
#pragma unroll
        for (int j = 0; j < 16; j++) acc[j] = 0ull;
        const float* xa = s_h + (ga*32 + r0)*XP;
        const float* xb = xa + 16*XP;
#pragma unroll 2
        for (int k4 = 0; k4 < 64; k4 += 4) {
            float4 va = *(const float4*)(xa + k4);
            float4 vb = *(const float4*)(xb + k4);
#pragma unroll
            for (int kk = 0; kk < 4; kk++) {
                u64 x0 = pack2((&va.x)[kk]);
                u64 x1 = pack2((&vb.x)[kk]);
                const ulonglong2* wp = (const ulonglong2*)(s_w + (k4+kk)*128 + c0);
                ulonglong2 w0 = wp[0], w1 = wp[1], w2 = wp[2], w3 = wp[3];
                ffma2(acc[0], x0, w0.x); ffma2(acc[1], x0, w0.y);
                ffma2(acc[2], x0, w1.x); ffma2(acc[3], x0, w1.y);
                ffma2(acc[4], x0, w2.x); ffma2(acc[5], x0, w2.y);
                ffma2(acc[6], x0, w3.x); ffma2(acc[7], x0, w3.y);
                ffma2(acc[8],  x1, w0.x); ffma2(acc[9],  x1, w0.y);
                ffma2(acc[10], x1, w1.x); ffma2(acc[11], x1, w1.y);
                ffma2(acc[12], x1, w2.x); ffma2(acc[13], x1, w2.y);
                ffma2(acc[14], x1, w3.x); ffma2(acc[15], x1, w3.y);
            }
        }
        // epilogue: stats + max/min over K=32 rows (2 in-reg + 16-lane shuffle tree)
        int gg = gg0 + ga;
        float* pmax = g_gmax + (size_t)gg*C2q + c0;
        float* pmin = g_gmin + (size_t)gg*C2q + c0;
        bool wr = (u & 15) == 0;
#pragma unroll
        for (int i = 0; i < 8; i++) {
            float2 a = unpack2(acc[i]);
            float2 b = unpack2(acc[8+i]);
            sum[2*i]   += a.x + b.x;  sq[2*i]   += a.x*a.x + b.x*b.x;
            sum[2*i+1] += a.y + b.y;  sq[2*i+1] += a.y*a.y + b.y*b.y;
            float mx0 = fmaxf(a.x, b.x), mn0 = fminf(a.x, b.x);
            float mx1 = fmaxf(a.y, b.y), mn1 = fminf(a.y, b.y);
#pragma unroll
            for (int off = 1; off < 16; off <<= 1) {
                mx0 = fmaxf(mx0, __shfl_xor_sync(0xffffffffu, mx0, off));
                mn0 = fminf(mn0, __shfl_xor_sync(0xffffffffu, mn0, off));
                mx1 = fmaxf(mx1, __shfl_xor_sync(0xffffffffu, mx1, off));
                mn1 = fminf(mn1, __shfl_xor_sync(0xffffffffu, mn1, off));
            }
            if (wr) {
                pmax[2*i]   = mx0;  pmin[2*i]   = mn0;
                pmax[2*i+1] = mx1;  pmin[2*i+1] = mn1;
            }
        }
    }
#pragma unroll
    for (int j = 0; j < 16; j++) {
        for (int off = 8; off; off >>= 1) {
            sum[j] += __shfl_xor_sync(0xffffffffu, sum[j], off);
            sq[j]  += __shfl_xor_sync(0xffffffffu, sq[j],  off);
        }
    }
    if ((u & 15) == 0) {
#pragma unroll
        for (int j = 0; j < 16; j++) {
            atomicAdd(&g_stats2[c0 + j],       sum[j]);
            atomicAdd(&g_stats2[C2q + c0 + j], sq[j]);
        }
    }
}

// ---------------- kernel 6: finalize output (affine + relu on per-group max/min) ----------------
__global__ __launch_bounds__(128) void final_kernel(float* __restrict__ out) {
    int c = threadIdx.x;
    float scale = g_sc2[c];
    float shift = g_sc2[C2q + c];
    for (int g = 0; g < 16; g++) {
        size_t gg = (size_t)blockIdx.x*16 + g;
        float v = (scale >= 0.f) ? g_gmax[gg*C2q + c] : g_gmin[gg*C2q + c];
        out[gg*C2q + c] = fmaxf(fmaf(v, scale, shift), 0.f);
    }
}

static const int GEMM1_SMEM = (68*64 + 4*32*XP) * (int)sizeof(float) + 128*(int)sizeof(int); // 52736
static const int GEMM2_SMEM = (64*128 + 2*32*XP + 128) * (int)sizeof(float);                  // 50688

extern "C" void kernel_launch(void* const* d_in, const int* in_sizes, int n_in,
                              void* d_out, int out_size) {
    (void)in_sizes; (void)n_in; (void)out_size;
    const float* pos  = (const float*)d_in[0];
    const float* feat = (const float*)d_in[1];
    const float* W1   = (const float*)d_in[2];
    const float* g1   = (const float*)d_in[3];
    const float* b1   = (const float*)d_in[4];
    const float* W2   = (const float*)d_in[5];
    const float* g2   = (const float*)d_in[6];
    const float* b2   = (const float*)d_in[7];
    float* out = (float*)d_out;

    cudaFuncSetAttribute(gemm1_kernel, cudaFuncAttributeMaxDynamicSharedMemorySize, GEMM1_SMEM);
    cudaFuncSetAttribute(gemm2_kernel, cudaFuncAttributeMaxDynamicSharedMemorySize, GEMM2_SMEM);

    // position passthrough (first output of the tuple)
    cudaMemcpyAsync(out, pos, (size_t)Bq*Nq*3*sizeof(float), cudaMemcpyDeviceToDevice, 0);

    zero_kernel<<<1, 256>>>();
    bq_kernel<<<dim3(Nq/64, Bq), 256>>>(pos);
    gemm1_kernel<<<GROUPS/32, 256, GEMM1_SMEM>>>(pos, feat, W1);
    fin1_kernel<<<1, C1q>>>(g1, b1);
    gemm2_kernel<<<GROUPS/16, 256, GEMM2_SMEM>>>(W2);
    fin2_kernel<<<1, C2q>>>(g2, b2);
    final_kernel<<<GROUPS/16, 128>>>(out + (size_t)Bq*Nq*3);
}

// round 6
// speedup vs baseline: 1.8499x; 1.3635x over previous
#include <cuda_runtime.h>

#define Bq 8
#define Nq 2048
#define Kq 32
#define C1q 64
#define C2q 128
#define GROUPS (Bq*Nq)        /* 16384 */
#define ROWS (GROUPS*Kq)      /* 524288 */
#define RAD2 (0.15f*0.15f)
#define EPSq 1e-5f
#define XP 68                 /* x-tile row stride: 68 mod 32 == 4 -> conflict-free LDS.128 */

typedef unsigned long long u64;

// ---------------- scratch (device globals: allocation-free rule) ----------------
__device__ int   g_idx[GROUPS*Kq];                    // 2 MB
__device__ float g_G[(size_t)GROUPS*C1q];             // 4 MB : [pos|feat] @ W1 per point
__device__ float g_P[(size_t)GROUPS*C1q];             // 4 MB : pos @ W1[0:3] per point
__device__ float g_gmax[(size_t)GROUPS*C2q];          // 8 MB
__device__ float g_gmin[(size_t)GROUPS*C2q];          // 8 MB
__device__ float g_stats1[2*C1q];
__device__ float g_stats2[2*C2q];
__device__ float g_sc1[2*C1q];
__device__ float g_sc2[2*C2q];

// ---------------- packed fp32x2 helpers ----------------
__device__ __forceinline__ void ffma2(u64 &d, u64 a, u64 b) {
    asm("fma.rn.f32x2 %0, %1, %2, %0;" : "+l"(d) : "l"(a), "l"(b));
}
__device__ __forceinline__ u64 pack2(float v) {
    u64 r; asm("mov.b64 %0, {%1, %1};" : "=l"(r) : "f"(v)); return r;
}
__device__ __forceinline__ float2 unpack2(u64 v) {
    float2 f; asm("mov.b64 {%0, %1}, %2;" : "=f"(f.x), "=f"(f.y) : "l"(v)); return f;
}

// ---------------- kernel: zero stats accumulators ----------------
__global__ void zero_kernel() {
    int t = threadIdx.x;
    if (t < 2*C1q) g_stats1[t] = 0.f;
    if (t < 2*C2q) g_stats2[t] = 0.f;
}

// ---------------- kernel: per-point transforms G = [pos|feat]@W1, P = pos@W1[0:3] ----------------
// thread = (point, 4-col quad): 16384 * 16 threads
__global__ __launch_bounds__(256) void pw_kernel(const float* __restrict__ pos,
                                                 const float* __restrict__ feat,
                                                 const float* __restrict__ W1) {
    __shared__ float s_w[67*64];
    int t = threadIdx.x;
    for (int i = t; i < 67*64; i += 256) s_w[i] = W1[i];
    __syncthreads();
    int gi = blockIdx.x*256 + t;
    int p = gi >> 4, c = (gi & 15) * 4;
    const float* pp = pos + (size_t)p*3;
    float px = pp[0], py = pp[1], pz = pp[2];
    float4 w0 = *(const float4*)(s_w + 0*64 + c);
    float4 w1 = *(const float4*)(s_w + 1*64 + c);
    float4 w2 = *(const float4*)(s_w + 2*64 + c);
    float4 P;
    P.x = fmaf(pz, w2.x, fmaf(py, w1.x, px*w0.x));
    P.y = fmaf(pz, w2.y, fmaf(py, w1.y, px*w0.y));
    P.z = fmaf(pz, w2.z, fmaf(py, w1.z, px*w0.z));
    P.w = fmaf(pz, w2.w, fmaf(py, w1.w, px*w0.w));
    float4 G = P;
    const float* fr = feat + (size_t)p*64;
#pragma unroll 4
    for (int k = 0; k < 64; k += 4) {
        float4 f = *(const float4*)(fr + k);
#pragma unroll
        for (int kk = 0; kk < 4; kk++) {
            float fv = (&f.x)[kk];
            float4 w = *(const float4*)(s_w + (3+k+kk)*64 + c);
            G.x = fmaf(fv, w.x, G.x);
            G.y = fmaf(fv, w.y, G.y);
            G.z = fmaf(fv, w.z, G.z);
            G.w = fmaf(fv, w.w, G.w);
        }
    }
    *(float4*)(g_G + (size_t)p*64 + c) = G;
    *(float4*)(g_P + (size_t)p*64 + c) = P;
}

// ---------------- kernel: ball query (one warp per center) ----------------
__global__ __launch_bounds__(256) void bq_kernel(const float* __restrict__ pos) {
    __shared__ float s_p[Nq*3];
    __shared__ float s_sq[Nq];
    __shared__ int   s_idx[8][Kq];
    int b = blockIdx.y;
    const float* pb = pos + (size_t)b*Nq*3;
    for (int i = threadIdx.x; i < Nq*3; i += blockDim.x) s_p[i] = pb[i];
    __syncthreads();
    for (int i = threadIdx.x; i < Nq; i += blockDim.x) {
        float x = s_p[3*i], y = s_p[3*i+1], z = s_p[3*i+2];
        s_sq[i] = x*x + y*y + z*z;
    }
    __syncthreads();
    int w = threadIdx.x >> 5, lane = threadIdx.x & 31;
    for (int it = 0; it < 8; it++) {
        int j = blockIdx.x*64 + it*8 + w;
        float cx = s_p[3*j], cy = s_p[3*j+1], cz = s_p[3*j+2];
        float csq = s_sq[j];
        int cnt = 0;
        for (int base = 0; base < Nq; base += 32) {
            int m = base + lane;
            float d = csq + s_sq[m]
                    - 2.0f*(cx*s_p[3*m] + cy*s_p[3*m+1] + cz*s_p[3*m+2]);
            bool v = !(d > RAD2);
            unsigned msk = __ballot_sync(0xffffffffu, v);
            int p = cnt + __popc(msk & ((1u << lane) - 1u));
            if (v && p < Kq) s_idx[w][p] = m;
            cnt += __popc(msk);
            if (cnt >= Kq) break;
        }
        __syncwarp();
        int first = s_idx[w][0];
        int nvalid = cnt < Kq ? cnt : Kq;
        int val = (lane < nvalid) ? s_idx[w][lane] : first;
        g_idx[((size_t)b*Nq + j)*Kq + lane] = val;
        __syncwarp();
    }
}

// ---------------- kernel: BN1 stats via gather of h1 = G[nb] - P[center] ----------------
// warp w handles cols [w*8, w*8+8); lane = row; 32 groups per block
__global__ __launch_bounds__(256) void stats1_kernel() {
    int t = threadIdx.x, w = t >> 5, lane = t & 31;
    int cb = w * 8;
    float sum[8], sq[8];
#pragma unroll
    for (int j = 0; j < 8; j++) { sum[j] = 0.f; sq[j] = 0.f; }
    for (int g = 0; g < 32; g++) {
        int gg = blockIdx.x*32 + g;
        int b = gg >> 11;
        int nb = g_idx[(size_t)gg*32 + lane];
        const float* gr = g_G + (((size_t)(b << 11) + nb) << 6) + cb;
        const float* pr = g_P + ((size_t)gg << 6) + cb;
        float4 a0 = *(const float4*)gr,     a1 = *(const float4*)(gr + 4);
        float4 p0 = *(const float4*)pr,     p1 = *(const float4*)(pr + 4);
        float h[8];
        h[0] = a0.x - p0.x; h[1] = a0.y - p0.y; h[2] = a0.z - p0.z; h[3] = a0.w - p0.w;
        h[4] = a1.x - p1.x; h[5] = a1.y - p1.y; h[6] = a1.z - p1.z; h[7] = a1.w - p1.w;
#pragma unroll
        for (int j = 0; j < 8; j++) { sum[j] += h[j]; sq[j] = fmaf(h[j], h[j], sq[j]); }
    }
#pragma unroll
    for (int j = 0; j < 8; j++) {
        for (int off = 16; off; off >>= 1) {
            sum[j] += __shfl_xor_sync(0xffffffffu, sum[j], off);
            sq[j]  += __shfl_xor_sync(0xffffffffu, sq[j],  off);
        }
    }
    if (lane == 0) {
#pragma unroll
        for (int j = 0; j < 8; j++) {
            atomicAdd(&g_stats1[cb + j],       sum[j]);
            atomicAdd(&g_stats1[C1q + cb + j], sq[j]);
        }
    }
}

// ---------------- finalize BN stats -> scale/shift ----------------
__global__ void fin1_kernel(const float* __restrict__ gamma, const float* __restrict__ beta) {
    int c = threadIdx.x;
    float inv = 1.0f / (float)ROWS;
    float mean = g_stats1[c] * inv;
    float var  = g_stats1[C1q + c] * inv - mean*mean;
    float sc   = gamma[c] * rsqrtf(var + EPSq);
    g_sc1[c] = sc;
    g_sc1[C1q + c] = beta[c] - mean*sc;
}
__global__ void fin2_kernel(const float* __restrict__ gamma, const float* __restrict__ beta) {
    int c = threadIdx.x;
    float inv = 1.0f / (float)ROWS;
    float mean = g_stats2[c] * inv;
    float var  = g_stats2[C2q + c] * inv - mean*mean;
    float sc   = gamma[c] * rsqrtf(var + EPSq);
    g_sc2[c] = sc;
    g_sc2[C2q + c] = beta[c] - mean*sc;
}

// ---------------- kernel: fused gather + BN1 + ReLU + GEMM2 + stats2 + group max/min ----------------
// 256 threads, 2 groups/iter, 8 iters -> 16 groups/block. Register double-buffered gather.
__global__ __launch_bounds__(256) void gemm2_kernel(const float* __restrict__ W2) {
    extern __shared__ float sm[];
    float* s_w  = sm;                 // 64*128
    float* s_h  = s_w + 64*128;       // 2 * 32 * XP
    float* s_sc = s_h + 2*32*XP;      // 128
    int t = threadIdx.x;
    for (int i = t; i < 64*128; i += 256) s_w[i] = W2[i];
    if (t < 128) s_sc[t] = g_sc1[t];
    int u = t & 127, ga = t >> 7;
    int r0 = u & 15, c0 = (u >> 4) * 16;
    float sum[16], sq[16];
#pragma unroll
    for (int j = 0; j < 16; j++) { sum[j] = 0.f; sq[j] = 0.f; }

    // per-thread tile-load coordinates (j = 0..3): i = t + 256*j
    float4 pg[4], pp[4];
#define LOADIT(IT)                                                            \
    {                                                                         \
        int gg0 = blockIdx.x*16 + (IT)*2;                                     \
        _Pragma("unroll")                                                     \
        for (int j = 0; j < 4; j++) {                                         \
            int i = t + 256*j;                                                \
            int g2 = i >> 9, rr = (i >> 4) & 31, c4 = i & 15;                 \
            int gg = gg0 + g2;                                                \
            int b = gg >> 11;                                                 \
            int nb = g_idx[(size_t)gg*32 + rr];                               \
            pg[j] = *(const float4*)(g_G + (((size_t)(b << 11) + nb) << 6) + c4*4); \
            pp[j] = *(const float4*)(g_P + ((size_t)gg << 6) + c4*4);         \
        }                                                                     \
    }

    LOADIT(0);
    for (int it = 0; it < 8; it++) {
        __syncthreads();                  // prior compute done with s_h (and s_sc ready on it 0)
#pragma unroll
        for (int j = 0; j < 4; j++) {     // normalize + relu -> s_h
            int i = t + 256*j;
            int g2 = i >> 9, rr = (i >> 4) & 31, c = (i & 15) * 4;
            float* xr = s_h + (g2*32 + rr)*XP + c;
            xr[0] = fmaxf(fmaf(pg[j].x - pp[j].x, s_sc[c+0], s_sc[64+c+0]), 0.f);
            xr[1] = fmaxf(fmaf(pg[j].y - pp[j].y, s_sc[c+1], s_sc[64+c+1]), 0.f);
            xr[2] = fmaxf(fmaf(pg[j].z - pp[j].z, s_sc[c+2], s_sc[64+c+2]), 0.f);
            xr[3] = fmaxf(fmaf(pg[j].w - pp[j].w, s_sc[c+3], s_sc[64+c+3]), 0.f);
        }
        __syncthreads();
        if (it < 7) LOADIT(it+1);         // prefetch next tile (overlaps compute below)

        u64 acc[16];
#pragma unroll
        for (int j = 0; j < 16; j++) acc[j] = 0ull;
        const float* xa = s_h + (ga*32 + r0)*XP;
        const float* xb = xa + 16*XP;
#pragma unroll 2
        for (int k4 = 0; k4 < 64; k4 += 4) {
            float4 va = *(const float4*)(xa + k4);
            float4 vb = *(const float4*)(xb + k4);
#pragma unroll
            for (int kk = 0; kk < 4; kk++) {
                u64 x0 = pack2((&va.x)[kk]);
                u64 x1 = pack2((&vb.x)[kk]);
                const ulonglong2* wp = (const ulonglong2*)(s_w + (k4+kk)*128 + c0);
                ulonglong2 w0 = wp[0], w1 = wp[1], w2 = wp[2], w3 = wp[3];
                ffma2(acc[0], x0, w0.x); ffma2(acc[1], x0, w0.y);
                ffma2(acc[2], x0, w1.x); ffma2(acc[3], x0, w1.y);
                ffma2(acc[4], x0, w2.x); ffma2(acc[5], x0, w2.y);
                ffma2(acc[6], x0, w3.x); ffma2(acc[7], x0, w3.y);
                ffma2(acc[8],  x1, w0.x); ffma2(acc[9],  x1, w0.y);
                ffma2(acc[10], x1, w1.x); ffma2(acc[11], x1, w1.y);
                ffma2(acc[12], x1, w2.x); ffma2(acc[13], x1, w2.y);
                ffma2(acc[14], x1, w3.x); ffma2(acc[15], x1, w3.y);
            }
        }
        // epilogue: stats + max/min over K=32 (2 in-reg + 16-lane shuffle tree)
        int gg = blockIdx.x*16 + it*2 + ga;
        float* pmax = g_gmax + (size_t)gg*C2q + c0;
        float* pmin = g_gmin + (size_t)gg*C2q + c0;
        bool wr = (u & 15) == 0;
#pragma unroll
        for (int i = 0; i < 8; i++) {
            float2 a = unpack2(acc[i]);
            float2 b = unpack2(acc[8+i]);
            sum[2*i]   += a.x + b.x;  sq[2*i]   += a.x*a.x + b.x*b.x;
            sum[2*i+1] += a.y + b.y;  sq[2*i+1] += a.y*a.y + b.y*b.y;
            float mx0 = fmaxf(a.x, b.x), mn0 = fminf(a.x, b.x);
            float mx1 = fmaxf(a.y, b.y), mn1 = fminf(a.y, b.y);
#pragma unroll
            for (int off = 1; off < 16; off <<= 1) {
                mx0 = fmaxf(mx0, __shfl_xor_sync(0xffffffffu, mx0, off));
                mn0 = fminf(mn0, __shfl_xor_sync(0xffffffffu, mn0, off));
                mx1 = fmaxf(mx1, __shfl_xor_sync(0xffffffffu, mx1, off));
                mn1 = fminf(mn1, __shfl_xor_sync(0xffffffffu, mn1, off));
            }
            if (wr) {
                pmax[2*i]   = mx0;  pmin[2*i]   = mn0;
                pmax[2*i+1] = mx1;  pmin[2*i+1] = mn1;
            }
        }
    }
#pragma unroll
    for (int j = 0; j < 16; j++) {
        for (int off = 8; off; off >>= 1) {
            sum[j] += __shfl_xor_sync(0xffffffffu, sum[j], off);
            sq[j]  += __shfl_xor_sync(0xffffffffu, sq[j],  off);
        }
    }
    if ((u & 15) == 0) {
#pragma unroll
        for (int j = 0; j < 16; j++) {
            atomicAdd(&g_stats2[c0 + j],       sum[j]);
            atomicAdd(&g_stats2[C2q + c0 + j], sq[j]);
        }
    }
#undef LOADIT
}

// ---------------- finalize output (affine + relu on per-group max/min) ----------------
__global__ __launch_bounds__(128) void final_kernel(float* __restrict__ out) {
    int c = threadIdx.x;
    float scale = g_sc2[c];
    float shift = g_sc2[C2q + c];
    for (int g = 0; g < 16; g++) {
        size_t gg = (size_t)blockIdx.x*16 + g;
        float v = (scale >= 0.f) ? g_gmax[gg*C2q + c] : g_gmin[gg*C2q + c];
        out[gg*C2q + c] = fmaxf(fmaf(v, scale, shift), 0.f);
    }
}

static const int GEMM2_SMEM = (64*128 + 2*32*XP + 128) * (int)sizeof(float);   // 50688 B

extern "C" void kernel_launch(void* const* d_in, const int* in_sizes, int n_in,
                              void* d_out, int out_size) {
    (void)in_sizes; (void)n_in; (void)out_size;
    const float* pos  = (const float*)d_in[0];
    const float* feat = (const float*)d_in[1];
    const float* W1   = (const float*)d_in[2];
    const float* g1   = (const float*)d_in[3];
    const float* b1   = (const float*)d_in[4];
    const float* W2   = (const float*)d_in[5];
    const float* g2   = (const float*)d_in[6];
    const float* b2   = (const float*)d_in[7];
    float* out = (float*)d_out;

    cudaFuncSetAttribute(gemm2_kernel, cudaFuncAttributeMaxDynamicSharedMemorySize, GEMM2_SMEM);

    zero_kernel<<<1, 256>>>();                       // launch 1
    pw_kernel<<<GROUPS*16/256, 256>>>(pos, feat, W1);// launch 2
    bq_kernel<<<dim3(Nq/64, Bq), 256>>>(pos);        // launch 3
    stats1_kernel<<<GROUPS/32, 256>>>();             // launch 4
    fin1_kernel<<<1, C1q>>>(g1, b1);                 // launch 5
    gemm2_kernel<<<GROUPS/16, 256, GEMM2_SMEM>>>(W2);// launch 6  (ncu -s 5 target)
    fin2_kernel<<<1, C2q>>>(g2, b2);
    final_kernel<<<GROUPS/16, 128>>>(out + (size_t)Bq*Nq*3);

    // position passthrough last (keeps gemm2 at ncu skip position regardless of
    // whether the memcpy node counts as a launch)
    cudaMemcpyAsync(out, pos, (size_t)Bq*Nq*3*sizeof(float), cudaMemcpyDeviceToDevice, 0);
}

// round 8
// speedup vs baseline: 2.2061x; 1.1926x over previous
#include <cuda_runtime.h>

#define Bq 8
#define Nq 2048
#define Kq 32
#define C1q 64
#define C2q 128
#define GROUPS (Bq*Nq)        /* 16384 */
#define ROWS (GROUPS*Kq)      /* 524288 */
#define RAD2 (0.15f*0.15f)
#define EPSq 1e-5f
#define XP 68                 /* x-tile row stride: 68 mod 32 == 4 -> conflict-free LDS.128 */

typedef unsigned long long u64;

// ---------------- scratch (device globals: allocation-free rule) ----------------
__device__ int   g_idx[GROUPS*Kq];                    // 2 MB
__device__ float g_G[(size_t)GROUPS*C1q];             // 4 MB : [pos|feat] @ W1 per point
__device__ float g_P[(size_t)GROUPS*C1q];             // 4 MB : pos @ W1[0:3] per point
__device__ float g_gmax[(size_t)GROUPS*C2q];          // 8 MB
__device__ float g_gmin[(size_t)GROUPS*C2q];          // 8 MB
__device__ float g_stats1[2*C1q];
__device__ float g_stats2[2*C2q];
__device__ float g_sc1[2*C1q];
__device__ float g_sc2[2*C2q];

// ---------------- packed fp32x2 helpers ----------------
__device__ __forceinline__ void ffma2(u64 &d, u64 a, u64 b) {
    asm("fma.rn.f32x2 %0, %1, %2, %0;" : "+l"(d) : "l"(a), "l"(b));
}
__device__ __forceinline__ u64 pack2(float v) {
    u64 r; asm("mov.b64 %0, {%1, %1};" : "=l"(r) : "f"(v)); return r;
}
__device__ __forceinline__ float2 unpack2(u64 v) {
    float2 f; asm("mov.b64 {%0, %1}, %2;" : "=f"(f.x), "=f"(f.y) : "l"(v)); return f;
}

// ---------------- kernel: zero stats accumulators ----------------
__global__ void zero_kernel() {
    int t = threadIdx.x;
    if (t < 2*C1q) g_stats1[t] = 0.f;
    if (t < 2*C2q) g_stats2[t] = 0.f;
}

// ---------------- kernel: per-point transforms + position passthrough ----------------
__global__ __launch_bounds__(256) void pw_kernel(const float* __restrict__ pos,
                                                 const float* __restrict__ feat,
                                                 const float* __restrict__ W1,
                                                 float* __restrict__ out) {
    __shared__ float s_w[67*64];
    int t = threadIdx.x;
    for (int i = t; i < 67*64; i += 256) s_w[i] = W1[i];
    // position passthrough: first 192 blocks copy 49152 floats
    if (blockIdx.x < 192) {
        int i = blockIdx.x*256 + t;
        out[i] = pos[i];
    }
    __syncthreads();
    int gi = blockIdx.x*256 + t;
    int p = gi >> 4, c = (gi & 15) * 4;
    const float* pp = pos + (size_t)p*3;
    float px = pp[0], py = pp[1], pz = pp[2];
    float4 w0 = *(const float4*)(s_w + 0*64 + c);
    float4 w1 = *(const float4*)(s_w + 1*64 + c);
    float4 w2 = *(const float4*)(s_w + 2*64 + c);
    float4 P;
    P.x = fmaf(pz, w2.x, fmaf(py, w1.x, px*w0.x));
    P.y = fmaf(pz, w2.y, fmaf(py, w1.y, px*w0.y));
    P.z = fmaf(pz, w2.z, fmaf(py, w1.z, px*w0.z));
    P.w = fmaf(pz, w2.w, fmaf(py, w1.w, px*w0.w));
    float4 G = P;
    const float* fr = feat + (size_t)p*64;
#pragma unroll 4
    for (int k = 0; k < 64; k += 4) {
        float4 f = *(const float4*)(fr + k);
#pragma unroll
        for (int kk = 0; kk < 4; kk++) {
            float fv = (&f.x)[kk];
            float4 w = *(const float4*)(s_w + (3+k+kk)*64 + c);
            G.x = fmaf(fv, w.x, G.x);
            G.y = fmaf(fv, w.y, G.y);
            G.z = fmaf(fv, w.z, G.z);
            G.w = fmaf(fv, w.w, G.w);
        }
    }
    *(float4*)(g_G + (size_t)p*64 + c) = G;
    *(float4*)(g_P + (size_t)p*64 + c) = P;
}

// ---------------- kernel: ball query (one warp per center, float4 point cache) ----------------
__global__ __launch_bounds__(256) void bq_kernel(const float* __restrict__ pos) {
    __shared__ float4 s_pq[Nq];
    __shared__ int    s_idx[8][Kq];
    int b = blockIdx.y;
    const float* pb = pos + (size_t)b*Nq*3;
    for (int i = threadIdx.x; i < Nq; i += 256) {
        float x = pb[3*i], y = pb[3*i+1], z = pb[3*i+2];
        s_pq[i] = make_float4(x, y, z, x*x + y*y + z*z);
    }
    __syncthreads();
    int w = threadIdx.x >> 5, lane = threadIdx.x & 31;
    for (int it = 0; it < 8; it++) {
        int j = blockIdx.x*64 + it*8 + w;
        float4 c = s_pq[j];
        int cnt = 0;
        for (int base = 0; base < Nq; base += 32) {
            float4 q = s_pq[base + lane];
            float d = c.w + q.w - 2.0f*(c.x*q.x + c.y*q.y + c.z*q.z);
            bool v = !(d > RAD2);
            unsigned msk = __ballot_sync(0xffffffffu, v);
            int p = cnt + __popc(msk & ((1u << lane) - 1u));
            if (v && p < Kq) s_idx[w][p] = base + lane;
            cnt += __popc(msk);
            if (cnt >= Kq) break;
        }
        __syncwarp();
        int first = s_idx[w][0];
        int nvalid = cnt < Kq ? cnt : Kq;
        int val = (lane < nvalid) ? s_idx[w][lane] : first;
        g_idx[((size_t)b*Nq + j)*Kq + lane] = val;
        __syncwarp();
    }
}

// ---------------- kernel: BN1 stats via cooperative row gather ----------------
// warp covers all 64 channels: lanes 0-15 = row 2i, lanes 16-31 = row 2i+1.
// 4 groups per warp, 8 warps per block, 512 blocks.
__global__ __launch_bounds__(256) void stats1_kernel() {
    __shared__ float s_part[8][128];
    int t = threadIdx.x, w = t >> 5, lane = t & 31;
    int c4 = (lane & 15) * 4;
    float sum[4] = {0.f,0.f,0.f,0.f}, sq[4] = {0.f,0.f,0.f,0.f};
    for (int g = 0; g < 4; g++) {
        int gg = (blockIdx.x*8 + w)*4 + g;
        int b = gg >> 11;
        int myidx = g_idx[(size_t)gg*32 + lane];
        float4 p4 = *(const float4*)(g_P + ((size_t)gg << 6) + c4);
        const float* Gb = g_G + ((size_t)(b << 11) << 6);
#pragma unroll 4
        for (int i = 0; i < 16; i++) {
            int nbA = __shfl_sync(0xffffffffu, myidx, 2*i);
            int nbB = __shfl_sync(0xffffffffu, myidx, 2*i+1);
            int nb = (lane < 16) ? nbA : nbB;
            float4 g4 = *(const float4*)(Gb + ((size_t)nb << 6) + c4);
            float h0 = g4.x - p4.x, h1 = g4.y - p4.y;
            float h2 = g4.z - p4.z, h3 = g4.w - p4.w;
            sum[0] += h0; sum[1] += h1; sum[2] += h2; sum[3] += h3;
            sq[0] = fmaf(h0,h0,sq[0]); sq[1] = fmaf(h1,h1,sq[1]);
            sq[2] = fmaf(h2,h2,sq[2]); sq[3] = fmaf(h3,h3,sq[3]);
        }
    }
#pragma unroll
    for (int j = 0; j < 4; j++) {
        sum[j] += __shfl_xor_sync(0xffffffffu, sum[j], 16);
        sq[j]  += __shfl_xor_sync(0xffffffffu, sq[j],  16);
    }
    if (lane < 16) {
#pragma unroll
        for (int j = 0; j < 4; j++) {
            s_part[w][c4 + j]      = sum[j];
            s_part[w][64 + c4 + j] = sq[j];
        }
    }
    __syncthreads();
    if (t < 128) {
        float v = 0.f;
#pragma unroll
        for (int w2 = 0; w2 < 8; w2++) v += s_part[w2][t];
        atomicAdd(&g_stats1[t], v);
    }
}

// ---------------- finalize BN stats -> scale/shift ----------------
__global__ void fin1_kernel(const float* __restrict__ gamma, const float* __restrict__ beta) {
    int c = threadIdx.x;
    float inv = 1.0f / (float)ROWS;
    float mean = g_stats1[c] * inv;
    float var  = g_stats1[C1q + c] * inv - mean*mean;
    float sc   = gamma[c] * rsqrtf(var + EPSq);
    g_sc1[c] = sc;
    g_sc1[C1q + c] = beta[c] - mean*sc;
}
__global__ void fin2_kernel(const float* __restrict__ gamma, const float* __restrict__ beta) {
    int c = threadIdx.x;
    float inv = 1.0f / (float)ROWS;
    float mean = g_stats2[c] * inv;
    float var  = g_stats2[C2q + c] * inv - mean*mean;
    float sc   = gamma[c] * rsqrtf(var + EPSq);
    g_sc2[c] = sc;
    g_sc2[C2q + c] = beta[c] - mean*sc;
}

// ---------------- kernel: fused gather + BN1 + ReLU + GEMM2 + stats2 + group max/min ----------------
__global__ __launch_bounds__(256) void gemm2_kernel(const float* __restrict__ W2) {
    extern __shared__ float sm[];
    float* s_w  = sm;                 // 64*128
    float* s_h  = s_w + 64*128;       // 2 * 32 * XP = 4352 (reused as reduce scratch, needs 4224)
    float* s_sc = s_h + 2*32*XP;      // 128
    int t = threadIdx.x;
    for (int i = t; i < 64*128; i += 256) s_w[i] = W2[i];
    if (t < 128) s_sc[t] = g_sc1[t];
    int u = t & 127, ga = t >> 7;
    int r0 = u & 15, c0 = (u >> 4) * 16;
    float sum[16], sq[16];
#pragma unroll
    for (int j = 0; j < 16; j++) { sum[j] = 0.f; sq[j] = 0.f; }

    float4 pg[4], pp[4];
#define LOADIT(IT)                                                            \
    {                                                                         \
        int gbase = blockIdx.x*16 + (IT)*2;                                   \
        _Pragma("unroll")                                                     \
        for (int j = 0; j < 4; j++) {                                         \
            int i = t + 256*j;                                                \
            int g2 = i >> 9, rr = (i >> 4) & 31, c4 = i & 15;                 \
            int gg = gbase + g2;                                              \
            int b = gg >> 11;                                                 \
            int nb = g_idx[(size_t)gg*32 + rr];                               \
            pg[j] = *(const float4*)(g_G + (((size_t)(b << 11) + nb) << 6) + c4*4); \
            pp[j] = *(const float4*)(g_P + ((size_t)gg << 6) + c4*4);         \
        }                                                                     \
    }

    LOADIT(0);
    for (int it = 0; it < 8; it++) {
        __syncthreads();                  // prior iteration done with s_h
#pragma unroll
        for (int j = 0; j < 4; j++) {     // normalize + relu -> s_h
            int i = t + 256*j;
            int g2 = i >> 9, rr = (i >> 4) & 31, c = (i & 15) * 4;
            float* xr = s_h + (g2*32 + rr)*XP + c;
            xr[0] = fmaxf(fmaf(pg[j].x - pp[j].x, s_sc[c+0], s_sc[64+c+0]), 0.f);
            xr[1] = fmaxf(fmaf(pg[j].y - pp[j].y, s_sc[c+1], s_sc[64+c+1]), 0.f);
            xr[2] = fmaxf(fmaf(pg[j].z - pp[j].z, s_sc[c+2], s_sc[64+c+2]), 0.f);
            xr[3] = fmaxf(fmaf(pg[j].w - pp[j].w, s_sc[c+3], s_sc[64+c+3]), 0.f);
        }
        __syncthreads();
        if (it < 7) LOADIT(it+1);         // register prefetch next tile

        u64 acc[16];
#pragma unroll
        for (int j = 0; j < 16; j++) acc[j] = 0ull;
        const float* xa = s_h + (ga*32 + r0)*XP;
        const float* xb = xa + 16*XP;
#pragma unroll 2
        for (int k4 = 0; k4 < 64; k4 += 4) {
            float4 va = *(const float4*)(xa + k4);
            float4 vb = *(const float4*)(xb + k4);
#pragma unroll
            for (int kk = 0; kk < 4; kk++) {
                u64 x0 = pack2((&va.x)[kk]);
                u64 x1 = pack2((&vb.x)[kk]);
                const ulonglong2* wp = (const ulonglong2*)(s_w + (k4+kk)*128 + c0);
                ulonglong2 w0 = wp[0], w1 = wp[1], w2 = wp[2], w3 = wp[3];
                ffma2(acc[0], x0, w0.x); ffma2(acc[1], x0, w0.y);
                ffma2(acc[2], x0, w1.x); ffma2(acc[3], x0, w1.y);
                ffma2(acc[4], x0, w2.x); ffma2(acc[5], x0, w2.y);
                ffma2(acc[6], x0, w3.x); ffma2(acc[7], x0, w3.y);
                ffma2(acc[8],  x1, w0.x); ffma2(acc[9],  x1, w0.y);
                ffma2(acc[10], x1, w1.x); ffma2(acc[11], x1, w1.y);
                ffma2(acc[12], x1, w2.x); ffma2(acc[13], x1, w2.y);
                ffma2(acc[14], x1, w3.x); ffma2(acc[15], x1, w3.y);
            }
        }
        // ---- epilogue: stats (regs) + group max/min via smem transpose-reduce ----
        int gbase = blockIdx.x*16 + it*2;
        __syncthreads();                  // mainloop reads of s_h complete
        float* wrp = s_h + (ga*16 + r0)*132 + c0;
#pragma unroll
        for (int i = 0; i < 8; i++) {
            float2 a = unpack2(acc[i]);
            float2 b = unpack2(acc[8+i]);
            sum[2*i]   += a.x + b.x;  sq[2*i]   += a.x*a.x + b.x*b.x;
            sum[2*i+1] += a.y + b.y;  sq[2*i+1] += a.y*a.y + b.y*b.y;
            *(float2*)(wrp + 2*i) = make_float2(fmaxf(a.x, b.x), fmaxf(a.y, b.y));
        }
        __syncthreads();
        {
            int g2r = t >> 7, chr = t & 127;
            const float* col = s_h + g2r*16*132 + chr;
            float m = col[0];
#pragma unroll
            for (int rr = 1; rr < 16; rr++) m = fmaxf(m, col[rr*132]);
            g_gmax[(size_t)(gbase + g2r)*C2q + chr] = m;
        }
        __syncthreads();
#pragma unroll
        for (int i = 0; i < 8; i++) {
            float2 a = unpack2(acc[i]);
            float2 b = unpack2(acc[8+i]);
            *(float2*)(wrp + 2*i) = make_float2(fminf(a.x, b.x), fminf(a.y, b.y));
        }
        __syncthreads();
        {
            int g2r = t >> 7, chr = t & 127;
            const float* col = s_h + g2r*16*132 + chr;
            float m = col[0];
#pragma unroll
            for (int rr = 1; rr < 16; rr++) m = fminf(m, col[rr*132]);
            g_gmin[(size_t)(gbase + g2r)*C2q + chr] = m;
        }
        // loop-top sync guards s_h reuse by next normalize
    }
#pragma unroll
    for (int j = 0; j < 16; j++) {
        for (int off = 8; off; off >>= 1) {
            sum[j] += __shfl_xor_sync(0xffffffffu, sum[j], off);
            sq[j]  += __shfl_xor_sync(0xffffffffu, sq[j],  off);
        }
    }
    if ((u & 15) == 0) {
#pragma unroll
        for (int j = 0; j < 16; j++) {
            atomicAdd(&g_stats2[c0 + j],       sum[j]);
            atomicAdd(&g_stats2[C2q + c0 + j], sq[j]);
        }
    }
#undef LOADIT
}

// ---------------- finalize output (affine + relu on per-group max/min) ----------------
__global__ __launch_bounds__(128) void final_kernel(float* __restrict__ out) {
    int c = threadIdx.x;
    float scale = g_sc2[c];
    float shift = g_sc2[C2q + c];
    for (int g = 0; g < 16; g++) {
        size_t gg = (size_t)blockIdx.x*16 + g;
        float v = (scale >= 0.f) ? g_gmax[gg*C2q + c] : g_gmin[gg*C2q + c];
        out[gg*C2q + c] = fmaxf(fmaf(v, scale, shift), 0.f);
    }
}

static const int GEMM2_SMEM = (64*128 + 2*32*XP + 128) * (int)sizeof(float);   // 50688 B

extern "C" void kernel_launch(void* const* d_in, const int* in_sizes, int n_in,
                              void* d_out, int out_size) {
    (void)in_sizes; (void)n_in; (void)out_size;
    const float* pos  = (const float*)d_in[0];
    const float* feat = (const float*)d_in[1];
    const float* W1   = (const float*)d_in[2];
    const float* g1   = (const float*)d_in[3];
    const float* b1   = (const float*)d_in[4];
    const float* W2   = (const float*)d_in[5];
    const float* g2   = (const float*)d_in[6];
    const float* b2   = (const float*)d_in[7];
    float* out = (float*)d_out;

    cudaFuncSetAttribute(gemm2_kernel, cudaFuncAttributeMaxDynamicSharedMemorySize, GEMM2_SMEM);

    zero_kernel<<<1, 256>>>();                         // 1
    pw_kernel<<<GROUPS*16/256, 256>>>(pos, feat, W1, out); // 2 (incl. position passthrough)
    bq_kernel<<<dim3(Nq/64, Bq), 256>>>(pos);          // 3
    stats1_kernel<<<GROUPS/32, 256>>>();               // 4
    fin1_kernel<<<1, C1q>>>(g1, b1);                   // 5
    gemm2_kernel<<<GROUPS/16, 256, GEMM2_SMEM>>>(W2);  // 6
    fin2_kernel<<<1, C2q>>>(g2, b2);                   // 7
    final_kernel<<<GROUPS/16, 128>>>(out + (size_t)Bq*Nq*3); // 8
}

// round 9
// speedup vs baseline: 2.3196x; 1.0514x over previous
#include <cuda_runtime.h>

#define Bq 8
#define Nq 2048
#define Kq 32
#define C1q 64
#define C2q 128
#define GROUPS (Bq*Nq)        /* 16384 */
#define ROWS (GROUPS*Kq)      /* 524288 */
#define RAD2 (0.15f*0.15f)
#define EPSq 1e-5f
#define XP 68                 /* h-tile row stride: 68 mod 32 == 4 -> conflict-free LDS.128 */
#define SP 132                /* epilogue scratch row stride */

typedef unsigned long long u64;

// ---------------- scratch (device globals: allocation-free rule) ----------------
__device__ int   g_idx[GROUPS*Kq];                    // 2 MB
__device__ float g_G[(size_t)GROUPS*C1q];             // 4 MB : [pos|feat] @ W1 per point
__device__ float g_P[(size_t)GROUPS*C1q];             // 4 MB : pos @ W1[0:3] per point
__device__ float g_gmax[(size_t)GROUPS*C2q];          // 8 MB
__device__ float g_gmin[(size_t)GROUPS*C2q];          // 8 MB
__device__ float g_stats1[2*C1q];
__device__ float g_stats2[2*C2q];
__device__ float g_sc1[2*C1q];
__device__ float g_sc2[2*C2q];

// ---------------- packed fp32x2 helpers ----------------
__device__ __forceinline__ void ffma2(u64 &d, u64 a, u64 b) {
    asm("fma.rn.f32x2 %0, %1, %2, %0;" : "+l"(d) : "l"(a), "l"(b));
}
__device__ __forceinline__ u64 pack2(float v) {
    u64 r; asm("mov.b64 %0, {%1, %1};" : "=l"(r) : "f"(v)); return r;
}
__device__ __forceinline__ float2 unpack2(u64 v) {
    float2 f; asm("mov.b64 {%0, %1}, %2;" : "=f"(f.x), "=f"(f.y) : "l"(v)); return f;
}

// ---------------- launch 1: per-point transforms + passthrough + stats zero ----------------
__global__ __launch_bounds__(256) void pw_kernel(const float* __restrict__ pos,
                                                 const float* __restrict__ feat,
                                                 const float* __restrict__ W1,
                                                 float* __restrict__ out) {
    __shared__ float s_w[67*64];
    int t = threadIdx.x;
    for (int i = t; i < 67*64; i += 256) s_w[i] = W1[i];
    if (blockIdx.x == 0) {                 // zero stats accumulators
        if (t < 128) g_stats1[t] = 0.f;
        g_stats2[t] = 0.f;                 // 256 entries
    }
    if (blockIdx.x < 192) {                // position passthrough (49152 floats)
        int i = blockIdx.x*256 + t;
        out[i] = pos[i];
    }
    __syncthreads();
    int gi = blockIdx.x*256 + t;
    int p = gi >> 4, c = (gi & 15) * 4;
    const float* pp = pos + (size_t)p*3;
    float px = pp[0], py = pp[1], pz = pp[2];
    float4 w0 = *(const float4*)(s_w + 0*64 + c);
    float4 w1 = *(const float4*)(s_w + 1*64 + c);
    float4 w2 = *(const float4*)(s_w + 2*64 + c);
    float4 P;
    P.x = fmaf(pz, w2.x, fmaf(py, w1.x, px*w0.x));
    P.y = fmaf(pz, w2.y, fmaf(py, w1.y, px*w0.y));
    P.z = fmaf(pz, w2.z, fmaf(py, w1.z, px*w0.z));
    P.w = fmaf(pz, w2.w, fmaf(py, w1.w, px*w0.w));
    float4 G = P;
    const float* fr = feat + (size_t)p*64;
#pragma unroll 4
    for (int k = 0; k < 64; k += 4) {
        float4 f = *(const float4*)(fr + k);
#pragma unroll
        for (int kk = 0; kk < 4; kk++) {
            float fv = (&f.x)[kk];
            float4 w = *(const float4*)(s_w + (3+k+kk)*64 + c);
            G.x = fmaf(fv, w.x, G.x);
            G.y = fmaf(fv, w.y, G.y);
            G.z = fmaf(fv, w.z, G.z);
            G.w = fmaf(fv, w.w, G.w);
        }
    }
    *(float4*)(g_G + (size_t)p*64 + c) = G;
    *(float4*)(g_P + (size_t)p*64 + c) = P;
}

// ---------------- launch 2: ball query + fused BN1-stats gather ----------------
// One warp per center. After the index list is built, the same warp gathers
// h1 = G[nb] - P[c] cooperatively (lanes 0-15 row 2i, 16-31 row 2i+1) and
// accumulates sum/sumsq — the L2-bound gather overlaps the issue-bound scan.
__global__ __launch_bounds__(256) void bq_kernel(const float* __restrict__ pos) {
    __shared__ float4 s_pq[Nq];
    __shared__ int    s_idx[8][Kq];
    __shared__ float  s_part[8][128];
    int b = blockIdx.y;
    const float* pb = pos + (size_t)b*Nq*3;
    for (int i = threadIdx.x; i < Nq; i += 256) {
        float x = pb[3*i], y = pb[3*i+1], z = pb[3*i+2];
        s_pq[i] = make_float4(x, y, z, x*x + y*y + z*z);
    }
    __syncthreads();
    int w = threadIdx.x >> 5, lane = threadIdx.x & 31;
    int c4 = (lane & 15) * 4;
    const float* Gb = g_G + (((size_t)b*Nq) << 6);
    float sum[4] = {0.f,0.f,0.f,0.f}, sq[4] = {0.f,0.f,0.f,0.f};
    for (int it = 0; it < 8; it++) {
        int j = blockIdx.x*64 + it*8 + w;
        float4 c = s_pq[j];
        int cnt = 0;
        for (int base = 0; base < Nq; base += 32) {
            float4 q = s_pq[base + lane];
            float d = c.w + q.w - 2.0f*(c.x*q.x + c.y*q.y + c.z*q.z);
            bool v = !(d > RAD2);
            unsigned msk = __ballot_sync(0xffffffffu, v);
            int p = cnt + __popc(msk & ((1u << lane) - 1u));
            if (v && p < Kq) s_idx[w][p] = base + lane;
            cnt += __popc(msk);
            if (cnt >= Kq) break;
        }
        __syncwarp();
        int first = s_idx[w][0];
        int nvalid = cnt < Kq ? cnt : Kq;
        int val = (lane < nvalid) ? s_idx[w][lane] : first;
        g_idx[((size_t)b*Nq + j)*Kq + lane] = val;
        // fused stats gather for this center
        float4 p4 = *(const float4*)(g_P + (((size_t)b*Nq + j) << 6) + c4);
#pragma unroll 4
        for (int i = 0; i < 16; i++) {
            int nbA = __shfl_sync(0xffffffffu, val, 2*i);
            int nbB = __shfl_sync(0xffffffffu, val, 2*i+1);
            int nb = (lane < 16) ? nbA : nbB;
            float4 g4 = *(const float4*)(Gb + ((size_t)nb << 6) + c4);
            float h0 = g4.x - p4.x, h1 = g4.y - p4.y;
            float h2 = g4.z - p4.z, h3 = g4.w - p4.w;
            sum[0] += h0; sum[1] += h1; sum[2] += h2; sum[3] += h3;
            sq[0] = fmaf(h0,h0,sq[0]); sq[1] = fmaf(h1,h1,sq[1]);
            sq[2] = fmaf(h2,h2,sq[2]); sq[3] = fmaf(h3,h3,sq[3]);
        }
        __syncwarp();
    }
#pragma unroll
    for (int j = 0; j < 4; j++) {
        sum[j] += __shfl_xor_sync(0xffffffffu, sum[j], 16);
        sq[j]  += __shfl_xor_sync(0xffffffffu, sq[j],  16);
    }
    if (lane < 16) {
#pragma unroll
        for (int j = 0; j < 4; j++) {
            s_part[w][c4 + j]      = sum[j];
            s_part[w][64 + c4 + j] = sq[j];
        }
    }
    __syncthreads();
    int t = threadIdx.x;
    if (t < 128) {
        float v = 0.f;
#pragma unroll
        for (int w2 = 0; w2 < 8; w2++) v += s_part[w2][t];
        atomicAdd(&g_stats1[t], v);
    }
}

// ---------------- launch 3/5: finalize BN stats -> scale/shift ----------------
__global__ void fin1_kernel(const float* __restrict__ gamma, const float* __restrict__ beta) {
    int c = threadIdx.x;
    float inv = 1.0f / (float)ROWS;
    float mean = g_stats1[c] * inv;
    float var  = g_stats1[C1q + c] * inv - mean*mean;
    float sc   = gamma[c] * rsqrtf(var + EPSq);
    g_sc1[c] = sc;
    g_sc1[C1q + c] = beta[c] - mean*sc;
}
__global__ void fin2_kernel(const float* __restrict__ gamma, const float* __restrict__ beta) {
    int c = threadIdx.x;
    float inv = 1.0f / (float)ROWS;
    float mean = g_stats2[c] * inv;
    float var  = g_stats2[C2q + c] * inv - mean*mean;
    float sc   = gamma[c] * rsqrtf(var + EPSq);
    g_sc2[c] = sc;
    g_sc2[C2q + c] = beta[c] - mean*sc;
}

// ---------------- launch 4: fused gather + BN1 + ReLU + GEMM2 + stats2 + group max/min ----------------
// 2048 blocks, 2 groups/iter, 4 iters. 2 CTAs/SM. Raw-value smem epilogue:
// one write pass; reducer thread per (group, channel) derives max/min/sum/sq.
__global__ __launch_bounds__(256, 2) void gemm2_kernel(const float* __restrict__ W2) {
    extern __shared__ float sm[];
    float* s_w   = sm;                 // 64*128 = 8192
    float* s_buf = sm + 8192;          // 8448: h-tile (64*XP=4352) / scratch (64*SP=8448)
    float* s_sc  = s_buf + 8448;       // 128
    int t = threadIdx.x;
    for (int i = t; i < 8192; i += 256) s_w[i] = W2[i];
    if (t < 128) s_sc[t] = g_sc1[t];
    int u = t & 127, ga = t >> 7;
    int r0 = u & 15, c0 = (u >> 4) * 16;
    int g2r = t >> 7, chr = t & 127;   // reducer identity
    float rsum = 0.f, rsq = 0.f;

    int nb[4];
#define LOADIDX(IT)                                                           \
    {                                                                         \
        int gb_ = blockIdx.x*8 + (IT)*2;                                      \
        _Pragma("unroll")                                                     \
        for (int j = 0; j < 4; j++) {                                         \
            int i = t + 256*j;                                                \
            int g2 = i >> 9, rr = (i >> 4) & 31;                              \
            nb[j] = g_idx[(size_t)(gb_ + g2)*32 + rr];                        \
        }                                                                     \
    }
    LOADIDX(0);
    for (int it = 0; it < 4; it++) {
        int gbase = blockIdx.x*8 + it*2;
        __syncthreads();                  // scratch reads done / s_w+s_sc ready
#pragma unroll
        for (int j = 0; j < 4; j++) {     // gather + normalize + relu -> s_buf (h layout)
            int i = t + 256*j;
            int g2 = i >> 9, rr = (i >> 4) & 31, c = (i & 15) * 4;
            int gg = gbase + g2;
            int b = gg >> 11;
            float4 g4 = *(const float4*)(g_G + (((size_t)(b << 11) + nb[j]) << 6) + c);
            float4 p4 = *(const float4*)(g_P + ((size_t)gg << 6) + c);
            float* xr = s_buf + (g2*32 + rr)*XP + c;
            xr[0] = fmaxf(fmaf(g4.x - p4.x, s_sc[c+0], s_sc[64+c+0]), 0.f);
            xr[1] = fmaxf(fmaf(g4.y - p4.y, s_sc[c+1], s_sc[64+c+1]), 0.f);
            xr[2] = fmaxf(fmaf(g4.z - p4.z, s_sc[c+2], s_sc[64+c+2]), 0.f);
            xr[3] = fmaxf(fmaf(g4.w - p4.w, s_sc[c+3], s_sc[64+c+3]), 0.f);
        }
        __syncthreads();
        if (it < 3) LOADIDX(it+1);        // prefetch next tile's indices only (4 regs)

        u64 acc[16];
#pragma unroll
        for (int j = 0; j < 16; j++) acc[j] = 0ull;
        const float* xa = s_buf + (ga*32 + r0)*XP;
        const float* xb = xa + 16*XP;
#pragma unroll 2
        for (int k4 = 0; k4 < 64; k4 += 4) {
            float4 va = *(const float4*)(xa + k4);
            float4 vb = *(const float4*)(xb + k4);
#pragma unroll
            for (int kk = 0; kk < 4; kk++) {
                u64 x0 = pack2((&va.x)[kk]);
                u64 x1 = pack2((&vb.x)[kk]);
                const ulonglong2* wp = (const ulonglong2*)(s_w + (k4+kk)*128 + c0);
                ulonglong2 w0 = wp[0], w1 = wp[1], w2 = wp[2], w3 = wp[3];
                ffma2(acc[0], x0, w0.x); ffma2(acc[1], x0, w0.y);
                ffma2(acc[2], x0, w1.x); ffma2(acc[3], x0, w1.y);
                ffma2(acc[4], x0, w2.x); ffma2(acc[5], x0, w2.y);
                ffma2(acc[6], x0, w3.x); ffma2(acc[7], x0, w3.y);
                ffma2(acc[8],  x1, w0.x); ffma2(acc[9],  x1, w0.y);
                ffma2(acc[10], x1, w1.x); ffma2(acc[11], x1, w1.y);
                ffma2(acc[12], x1, w2.x); ffma2(acc[13], x1, w2.y);
                ffma2(acc[14], x1, w3.x); ffma2(acc[15], x1, w3.y);
            }
        }
        __syncthreads();                  // mainloop reads of s_buf complete
        // single raw-value write pass (rows r0 and r0+16 of group ga)
        float* wr0 = s_buf + (ga*32 + r0)*SP + c0;
        float* wr1 = wr0 + 16*SP;
#pragma unroll
        for (int i = 0; i < 8; i++) {
            *(float2*)(wr0 + 2*i) = unpack2(acc[i]);
            *(float2*)(wr1 + 2*i) = unpack2(acc[8+i]);
        }
        __syncthreads();
        // reducer: one thread per (group, channel): max/min/sum/sumsq over K=32
        {
            const float* col = s_buf + g2r*32*SP + chr;
            float v = col[0];
            float mx = v, mn = v, s = v, s2 = v*v;
#pragma unroll
            for (int rr = 1; rr < 32; rr++) {
                float x = col[rr*SP];
                mx = fmaxf(mx, x); mn = fminf(mn, x);
                s += x; s2 = fmaf(x, x, s2);
            }
            g_gmax[(size_t)(gbase + g2r)*C2q + chr] = mx;
            g_gmin[(size_t)(gbase + g2r)*C2q + chr] = mn;
            rsum += s; rsq += s2;
        }
        // loop-top sync guards scratch reuse by next normalize
    }
    atomicAdd(&g_stats2[chr], rsum);
    atomicAdd(&g_stats2[C2q + chr], rsq);
#undef LOADIDX
}

// ---------------- launch 6: finalize output (affine + relu on per-group max/min) ----------------
__global__ __launch_bounds__(128) void final_kernel(float* __restrict__ out) {
    int c = threadIdx.x;
    float scale = g_sc2[c];
    float shift = g_sc2[C2q + c];
    for (int g = 0; g < 16; g++) {
        size_t gg = (size_t)blockIdx.x*16 + g;
        float v = (scale >= 0.f) ? g_gmax[gg*C2q + c] : g_gmin[gg*C2q + c];
        out[gg*C2q + c] = fmaxf(fmaf(v, scale, shift), 0.f);
    }
}

static const int GEMM2_SMEM = (8192 + 8448 + 128) * (int)sizeof(float);   // 67072 B

extern "C" void kernel_launch(void* const* d_in, const int* in_sizes, int n_in,
                              void* d_out, int out_size) {
    (void)in_sizes; (void)n_in; (void)out_size;
    const float* pos  = (const float*)d_in[0];
    const float* feat = (const float*)d_in[1];
    const float* W1   = (const float*)d_in[2];
    const float* g1   = (const float*)d_in[3];
    const float* b1   = (const float*)d_in[4];
    const float* W2   = (const float*)d_in[5];
    const float* g2   = (const float*)d_in[6];
    const float* b2   = (const float*)d_in[7];
    float* out = (float*)d_out;

    cudaFuncSetAttribute(gemm2_kernel, cudaFuncAttributeMaxDynamicSharedMemorySize, GEMM2_SMEM);

    pw_kernel<<<GROUPS*16/256, 256>>>(pos, feat, W1, out);  // 1
    bq_kernel<<<dim3(Nq/64, Bq), 256>>>(pos);               // 2 (incl. BN1 stats)
    fin1_kernel<<<1, C1q>>>(g1, b1);                        // 3
    gemm2_kernel<<<GROUPS/8, 256, GEMM2_SMEM>>>(W2);        // 4  <- profiled slot
    fin2_kernel<<<1, C2q>>>(g2, b2);                        // 5
    final_kernel<<<GROUPS/16, 128>>>(out + (size_t)Bq*Nq*3);// 6
}

// round 10
// speedup vs baseline: 2.4092x; 1.0386x over previous
#include <cuda_runtime.h>

#define Bq 8
#define Nq 2048
#define Kq 32
#define C1q 64
#define C2q 128
#define GROUPS (Bq*Nq)        /* 16384 */
#define ROWS (GROUPS*Kq)      /* 524288 */
#define RAD2 (0.15f*0.15f)
#define EPSq 1e-5f
#define XP 68                 /* h-tile row stride: rb-stride 68 -> 17 quads == 1 mod 8, conflict-free */
#define SP 132                /* epilogue scratch row stride */

typedef unsigned long long u64;

// ---------------- scratch (device globals: allocation-free rule) ----------------
__device__ int   g_idx[GROUPS*Kq];                    // 2 MB
__device__ float g_G[(size_t)GROUPS*C1q];             // 4 MB : [pos|feat] @ W1 per point
__device__ float g_P[(size_t)GROUPS*C1q];             // 4 MB : pos @ W1[0:3] per point
__device__ float g_gmax[(size_t)GROUPS*C2q];          // 8 MB
__device__ float g_gmin[(size_t)GROUPS*C2q];          // 8 MB
__device__ float g_stats1[2*C1q];
__device__ float g_stats2[2*C2q];
__device__ float g_sc1[2*C1q];
__device__ float g_sc2[2*C2q];

// ---------------- packed fp32x2 helpers ----------------
__device__ __forceinline__ void ffma2(u64 &d, u64 a, u64 b) {
    asm("fma.rn.f32x2 %0, %1, %2, %0;" : "+l"(d) : "l"(a), "l"(b));
}
__device__ __forceinline__ u64 pack2(float v) {
    u64 r; asm("mov.b64 %0, {%1, %1};" : "=l"(r) : "f"(v)); return r;
}
__device__ __forceinline__ float2 unpack2(u64 v) {
    float2 f; asm("mov.b64 {%0, %1}, %2;" : "=f"(f.x), "=f"(f.y) : "l"(v)); return f;
}

// ---------------- launch 1: per-point transforms + passthrough + stats zero ----------------
__global__ __launch_bounds__(256) void pw_kernel(const float* __restrict__ pos,
                                                 const float* __restrict__ feat,
                                                 const float* __restrict__ W1,
                                                 float* __restrict__ out) {
    __shared__ float s_w[67*64];
    int t = threadIdx.x;
    for (int i = t; i < 67*64; i += 256) s_w[i] = W1[i];
    if (blockIdx.x == 0) {                 // zero stats accumulators
        if (t < 128) g_stats1[t] = 0.f;
        g_stats2[t] = 0.f;
    }
    if (blockIdx.x < 192) {                // position passthrough (49152 floats)
        int i = blockIdx.x*256 + t;
        out[i] = pos[i];
    }
    __syncthreads();
    int gi = blockIdx.x*256 + t;
    int p = gi >> 4, c = (gi & 15) * 4;
    const float* pp = pos + (size_t)p*3;
    float px = pp[0], py = pp[1], pz = pp[2];
    float4 w0 = *(const float4*)(s_w + 0*64 + c);
    float4 w1 = *(const float4*)(s_w + 1*64 + c);
    float4 w2 = *(const float4*)(s_w + 2*64 + c);
    float4 P;
    P.x = fmaf(pz, w2.x, fmaf(py, w1.x, px*w0.x));
    P.y = fmaf(pz, w2.y, fmaf(py, w1.y, px*w0.y));
    P.z = fmaf(pz, w2.z, fmaf(py, w1.z, px*w0.z));
    P.w = fmaf(pz, w2.w, fmaf(py, w1.w, px*w0.w));
    float4 G = P;
    const float* fr = feat + (size_t)p*64;
#pragma unroll 4
    for (int k = 0; k < 64; k += 4) {
        float4 f = *(const float4*)(fr + k);
#pragma unroll
        for (int kk = 0; kk < 4; kk++) {
            float fv = (&f.x)[kk];
            float4 w = *(const float4*)(s_w + (3+k+kk)*64 + c);
            G.x = fmaf(fv, w.x, G.x);
            G.y = fmaf(fv, w.y, G.y);
            G.z = fmaf(fv, w.z, G.z);
            G.w = fmaf(fv, w.w, G.w);
        }
    }
    *(float4*)(g_G + (size_t)p*64 + c) = G;
    *(float4*)(g_P + (size_t)p*64 + c) = P;
}

// ---------------- launch 2: ball query + fused BN1-stats gather ----------------
__global__ __launch_bounds__(256) void bq_kernel(const float* __restrict__ pos) {
    __shared__ float4 s_pq[Nq];
    __shared__ int    s_idx[8][Kq];
    __shared__ float  s_part[8][128];
    int b = blockIdx.y;
    const float* pb = pos + (size_t)b*Nq*3;
    for (int i = threadIdx.x; i < Nq; i += 256) {
        float x = pb[3*i], y = pb[3*i+1], z = pb[3*i+2];
        s_pq[i] = make_float4(x, y, z, x*x + y*y + z*z);
    }
    __syncthreads();
    int w = threadIdx.x >> 5, lane = threadIdx.x & 31;
    int c4 = (lane & 15) * 4;
    const float* Gb = g_G + (((size_t)b*Nq) << 6);
    float sum[4] = {0.f,0.f,0.f,0.f}, sq[4] = {0.f,0.f,0.f,0.f};
    for (int it = 0; it < 8; it++) {
        int j = blockIdx.x*64 + it*8 + w;
        float4 c = s_pq[j];
        int cnt = 0;
        for (int base = 0; base < Nq; base += 32) {
            float4 q = s_pq[base + lane];
            float d = c.w + q.w - 2.0f*(c.x*q.x + c.y*q.y + c.z*q.z);
            bool v = !(d > RAD2);
            unsigned msk = __ballot_sync(0xffffffffu, v);
            int p = cnt + __popc(msk & ((1u << lane) - 1u));
            if (v && p < Kq) s_idx[w][p] = base + lane;
            cnt += __popc(msk);
            if (cnt >= Kq) break;
        }
        __syncwarp();
        int first = s_idx[w][0];
        int nvalid = cnt < Kq ? cnt : Kq;
        int val = (lane < nvalid) ? s_idx[w][lane] : first;
        g_idx[((size_t)b*Nq + j)*Kq + lane] = val;
        float4 p4 = *(const float4*)(g_P + (((size_t)b*Nq + j) << 6) + c4);
#pragma unroll 4
        for (int i = 0; i < 16; i++) {
            int nbA = __shfl_sync(0xffffffffu, val, 2*i);
            int nbB = __shfl_sync(0xffffffffu, val, 2*i+1);
            int nb = (lane < 16) ? nbA : nbB;
            float4 g4 = *(const float4*)(Gb + ((size_t)nb << 6) + c4);
            float h0 = g4.x - p4.x, h1 = g4.y - p4.y;
            float h2 = g4.z - p4.z, h3 = g4.w - p4.w;
            sum[0] += h0; sum[1] += h1; sum[2] += h2; sum[3] += h3;
            sq[0] = fmaf(h0,h0,sq[0]); sq[1] = fmaf(h1,h1,sq[1]);
            sq[2] = fmaf(h2,h2,sq[2]); sq[3] = fmaf(h3,h3,sq[3]);
        }
        __syncwarp();
    }
#pragma unroll
    for (int j = 0; j < 4; j++) {
        sum[j] += __shfl_xor_sync(0xffffffffu, sum[j], 16);
        sq[j]  += __shfl_xor_sync(0xffffffffu, sq[j],  16);
    }
    if (lane < 16) {
#pragma unroll
        for (int j = 0; j < 4; j++) {
            s_part[w][c4 + j]      = sum[j];
            s_part[w][64 + c4 + j] = sq[j];
        }
    }
    __syncthreads();
    int t = threadIdx.x;
    if (t < 128) {
        float v = 0.f;
#pragma unroll
        for (int w2 = 0; w2 < 8; w2++) v += s_part[w2][t];
        atomicAdd(&g_stats1[t], v);
    }
}

// ---------------- launch 3/5: finalize BN stats -> scale/shift ----------------
__global__ void fin1_kernel(const float* __restrict__ gamma, const float* __restrict__ beta) {
    int c = threadIdx.x;
    float inv = 1.0f / (float)ROWS;
    float mean = g_stats1[c] * inv;
    float var  = g_stats1[C1q + c] * inv - mean*mean;
    float sc   = gamma[c] * rsqrtf(var + EPSq);
    g_sc1[c] = sc;
    g_sc1[C1q + c] = beta[c] - mean*sc;
}
__global__ void fin2_kernel(const float* __restrict__ gamma, const float* __restrict__ beta) {
    int c = threadIdx.x;
    float inv = 1.0f / (float)ROWS;
    float mean = g_stats2[c] * inv;
    float var  = g_stats2[C2q + c] * inv - mean*mean;
    float sc   = gamma[c] * rsqrtf(var + EPSq);
    g_sc2[c] = sc;
    g_sc2[C2q + c] = beta[c] - mean*sc;
}

// ---------------- launch 4: fused gather + BN1 + ReLU + GEMM2 + stats2 + group max/min ----------------
// 2048 blocks, 4 groups (128 rows) per iter, 2 iters. Thread tile 8 rows x 8 cols,
// rows interleaved stride-8 (conflict-free x LDS.128). Bytes/MAC = 1.0 (crossbar-balanced).
__global__ __launch_bounds__(256, 2) void gemm2_kernel(const float* __restrict__ W2) {
    extern __shared__ float sm[];
    float* s_w  = sm;                  // 64*128 = 8192
    float* s_h  = sm + 8192;           // 128*XP = 8704  (epilogue scratch: 64*SP = 8448)
    float* s_sc = s_h + 8704;          // 128
    int t = threadIdx.x;
    for (int i = t; i < 8192; i += 256) s_w[i] = W2[i];
    if (t < 128) s_sc[t] = g_sc1[t];
    int rh = t >> 7, u = t & 127;
    int rb = u & 7, cb = u >> 3;       // cb 0..15 (8 cols each)
    int g2r = t >> 7, chr = t & 127;   // reducer identity
    float rsum = 0.f, rsq = 0.f;

    int nb[8];
#define LOADIDX(IT)                                                           \
    {                                                                         \
        int gb_ = blockIdx.x*8 + (IT)*4;                                      \
        _Pragma("unroll")                                                     \
        for (int j = 0; j < 8; j++) {                                         \
            int i = t + 256*j;                                                \
            int g2 = i >> 9, rr = (i >> 4) & 31;                              \
            nb[j] = g_idx[(size_t)(gb_ + g2)*32 + rr];                        \
        }                                                                     \
    }
    LOADIDX(0);
    for (int it = 0; it < 2; it++) {
        int gbase = blockIdx.x*8 + it*4;
        __syncthreads();                  // scratch/reducer reads done; s_w/s_sc ready
#pragma unroll
        for (int j = 0; j < 8; j++) {     // gather + normalize + relu -> s_h (128 rows)
            int i = t + 256*j;
            int g2 = i >> 9, rr = (i >> 4) & 31, c = (i & 15) * 4;
            int gg = gbase + g2;
            int b = gg >> 11;
            float4 g4 = *(const float4*)(g_G + (((size_t)(b << 11) + nb[j]) << 6) + c);
            float4 p4 = *(const float4*)(g_P + ((size_t)gg << 6) + c);
            float* xr = s_h + (g2*32 + rr)*XP + c;
            xr[0] = fmaxf(fmaf(g4.x - p4.x, s_sc[c+0], s_sc[64+c+0]), 0.f);
            xr[1] = fmaxf(fmaf(g4.y - p4.y, s_sc[c+1], s_sc[64+c+1]), 0.f);
            xr[2] = fmaxf(fmaf(g4.z - p4.z, s_sc[c+2], s_sc[64+c+2]), 0.f);
            xr[3] = fmaxf(fmaf(g4.w - p4.w, s_sc[c+3], s_sc[64+c+3]), 0.f);
        }
        __syncthreads();
        if (it == 0) LOADIDX(1);          // prefetch next tile's indices (8 regs)

        u64 acc[8][4];
#pragma unroll
        for (int j = 0; j < 8; j++)
#pragma unroll
            for (int q = 0; q < 4; q++) acc[j][q] = 0ull;
        const float* xbp = s_h + (rh*64 + rb)*XP;    // rows rh*64 + rb + 8j
        const float* wbp = s_w + cb*8;
#pragma unroll 2
        for (int k4 = 0; k4 < 64; k4 += 4) {
            float4 xv[8];
#pragma unroll
            for (int j = 0; j < 8; j++)
                xv[j] = *(const float4*)(xbp + j*8*XP + k4);
#pragma unroll
            for (int kk = 0; kk < 4; kk++) {
                const float* wr = wbp + (k4+kk)*128;
                ulonglong2 wA = *(const ulonglong2*)wr;
                ulonglong2 wB = *(const ulonglong2*)(wr + 4);
#pragma unroll
                for (int j = 0; j < 8; j++) {
                    u64 xx = pack2((&xv[j].x)[kk]);
                    ffma2(acc[j][0], xx, wA.x);
                    ffma2(acc[j][1], xx, wA.y);
                    ffma2(acc[j][2], xx, wB.x);
                    ffma2(acc[j][3], xx, wB.y);
                }
            }
        }
        // ---- epilogue: two row-half passes through 64-row scratch ----
#pragma unroll
        for (int p = 0; p < 2; p++) {
            __syncthreads();              // p=0: mainloop s_h reads done; p=1: reducers done
            if (rh == p) {
#pragma unroll
                for (int j = 0; j < 8; j++) {
                    float* wr = s_h + (rb + 8*j)*SP + cb*8;
                    *(float2*)(wr + 0) = unpack2(acc[j][0]);
                    *(float2*)(wr + 2) = unpack2(acc[j][1]);
                    *(float2*)(wr + 4) = unpack2(acc[j][2]);
                    *(float2*)(wr + 6) = unpack2(acc[j][3]);
                }
            }
            __syncthreads();
            {   // reducer: one thread per (group, channel) over K=32 rows
                const float* col = s_h + g2r*32*SP + chr;
                float v = col[0];
                float mx = v, mn = v, s = v, s2 = v*v;
#pragma unroll
                for (int rr = 1; rr < 32; rr++) {
                    float x = col[rr*SP];
                    mx = fmaxf(mx, x); mn = fminf(mn, x);
                    s += x; s2 = fmaf(x, x, s2);
                }
                size_t gg = (size_t)(gbase + p*2 + g2r);
                g_gmax[gg*C2q + chr] = mx;
                g_gmin[gg*C2q + chr] = mn;
                rsum += s; rsq += s2;
            }
        }
        // loop-top sync guards s_h reuse by next gather
    }
    atomicAdd(&g_stats2[chr], rsum);
    atomicAdd(&g_stats2[C2q + chr], rsq);
#undef LOADIDX
}

// ---------------- launch 6: finalize output (affine + relu on per-group max/min) ----------------
__global__ __launch_bounds__(128) void final_kernel(float* __restrict__ out) {
    int c = threadIdx.x;
    float scale = g_sc2[c];
    float shift = g_sc2[C2q + c];
    for (int g = 0; g < 16; g++) {
        size_t gg = (size_t)blockIdx.x*16 + g;
        float v = (scale >= 0.f) ? g_gmax[gg*C2q + c] : g_gmin[gg*C2q + c];
        out[gg*C2q + c] = fmaxf(fmaf(v, scale, shift), 0.f);
    }
}

static const int GEMM2_SMEM = (8192 + 8704 + 128) * (int)sizeof(float);   // 68096 B

extern "C" void kernel_launch(void* const* d_in, const int* in_sizes, int n_in,
                              void* d_out, int out_size) {
    (void)in_sizes; (void)n_in; (void)out_size;
    const float* pos  = (const float*)d_in[0];
    const float* feat = (const float*)d_in[1];
    const float* W1   = (const float*)d_in[2];
    const float* g1   = (const float*)d_in[3];
    const float* b1   = (const float*)d_in[4];
    const float* W2   = (const float*)d_in[5];
    const float* g2   = (const float*)d_in[6];
    const float* b2   = (const float*)d_in[7];
    float* out = (float*)d_out;

    cudaFuncSetAttribute(gemm2_kernel, cudaFuncAttributeMaxDynamicSharedMemorySize, GEMM2_SMEM);

    pw_kernel<<<GROUPS*16/256, 256>>>(pos, feat, W1, out);  // 1
    bq_kernel<<<dim3(Nq/64, Bq), 256>>>(pos);               // 2 (incl. BN1 stats)
    fin1_kernel<<<1, C1q>>>(g1, b1);                        // 3
    gemm2_kernel<<<GROUPS/8, 256, GEMM2_SMEM>>>(W2);        // 4  <- profiled slot
    fin2_kernel<<<1, C2q>>>(g2, b2);                        // 5
    final_kernel<<<GROUPS/16, 128>>>(out + (size_t)Bq*Nq*3);// 6
}

// round 12
// speedup vs baseline: 3.4936x; 1.4501x over previous
#include <cuda_runtime.h>
#include <cuda_bf16.h>
#include <cstdint>

#define Bq 8
#define Nq 2048
#define Kq 32
#define C1q 64
#define C2q 128
#define GROUPS (Bq*Nq)        /* 16384 */
#define ROWS (GROUPS*Kq)      /* 524288 */
#define RAD2 (0.15f*0.15f)
#define EPSq 1e-5f

typedef unsigned long long u64;

// ---------------- scratch (device globals: allocation-free rule) ----------------
__device__ int      g_idx[GROUPS*Kq];                 // 2 MB
__device__ float    g_G[(size_t)GROUPS*C1q];          // 4 MB
__device__ float    g_P[(size_t)GROUPS*C1q];          // 4 MB
__device__ float    g_gmax[(size_t)GROUPS*C2q];       // 8 MB
__device__ float    g_gmin[(size_t)GROUPS*C2q];       // 8 MB
__device__ uint32_t g_Bh[4096];                       // W2^T bf16-hi, SW128-swizzled [n][k] image
__device__ uint32_t g_Bl[4096];                       // W2^T bf16-lo
__device__ float    g_stats1[2*C1q];
__device__ float    g_stats2[2*C2q];
__device__ float    g_sc1[2*C1q];
__device__ float    g_sc2[2*C2q];

// ---------------- helpers ----------------
__device__ __forceinline__ uint32_t smem_u32(const void* p) {
    uint32_t a;
    asm("{ .reg .u64 tmp; cvta.to.shared.u64 tmp, %1; cvt.u32.u64 %0, tmp; }"
        : "=r"(a) : "l"(p));
    return a;
}
#define SW128(off) ((off) ^ (((off) >> 3) & 0x70))

// warp-level bf16 MMA (baseline PTX, works on compute_103)
#define MMA16816(c, a, b0, b1) \
    asm volatile("mma.sync.aligned.m16n8k16.row.col.f32.bf16.bf16.f32 " \
        "{%0,%1,%2,%3}, {%4,%5,%6,%7}, {%8,%9}, {%0,%1,%2,%3};" \
        : "+f"((c)[0]), "+f"((c)[1]), "+f"((c)[2]), "+f"((c)[3]) \
        : "r"((a)[0]), "r"((a)[1]), "r"((a)[2]), "r"((a)[3]), "r"(b0), "r"(b1))

#define LDSM4(r, addr) \
    asm volatile("ldmatrix.sync.aligned.m8n8.x4.shared.b16 {%0,%1,%2,%3}, [%4];" \
        : "=r"((r)[0]), "=r"((r)[1]), "=r"((r)[2]), "=r"((r)[3]) : "r"(addr))

// ---------------- launch 1: per-point transforms + passthrough + W2 images + zero ----------------
__global__ __launch_bounds__(256) void pw_kernel(const float* __restrict__ pos,
                                                 const float* __restrict__ feat,
                                                 const float* __restrict__ W1,
                                                 const float* __restrict__ W2,
                                                 float* __restrict__ out) {
    __shared__ float s_w[67*64];
    int t = threadIdx.x;
    for (int i = t; i < 67*64; i += 256) s_w[i] = W1[i];
    if (blockIdx.x == 0) {                 // zero stats accumulators
        if (t < 128) g_stats1[t] = 0.f;
        g_stats2[t] = 0.f;
    }
    if (blockIdx.x < 192) {                // position passthrough
        int i = blockIdx.x*256 + t;
        out[i] = pos[i];
    }
    if (blockIdx.x < 16) {                 // build swizzled bf16 images of W2^T [n=128][k=64]
        int idx = blockIdx.x*256 + t;      // 0..4095: n = channel row, j = k-pair
        int n = idx >> 5, j = idx & 31;
        float w0 = W2[(2*j)*128 + n];
        float w1 = W2[(2*j+1)*128 + n];
        __nv_bfloat162 hi;
        hi.x = __float2bfloat16(w0);
        hi.y = __float2bfloat16(w1);
        __nv_bfloat162 lo;
        lo.x = __float2bfloat16(w0 - __bfloat162float(hi.x));
        lo.y = __float2bfloat16(w1 - __bfloat162float(hi.y));
        uint32_t off = (uint32_t)(n*128 + j*4);
        uint32_t sw = SW128(off) >> 2;
        g_Bh[sw] = *(uint32_t*)&hi;
        g_Bl[sw] = *(uint32_t*)&lo;
    }
    __syncthreads();
    int gi = blockIdx.x*256 + t;
    int p = gi >> 4, c = (gi & 15) * 4;
    const float* pp = pos + (size_t)p*3;
    float px = pp[0], py = pp[1], pz = pp[2];
    float4 w0 = *(const float4*)(s_w + 0*64 + c);
    float4 w1 = *(const float4*)(s_w + 1*64 + c);
    float4 w2 = *(const float4*)(s_w + 2*64 + c);
    float4 P;
    P.x = fmaf(pz, w2.x, fmaf(py, w1.x, px*w0.x));
    P.y = fmaf(pz, w2.y, fmaf(py, w1.y, px*w0.y));
    P.z = fmaf(pz, w2.z, fmaf(py, w1.z, px*w0.z));
    P.w = fmaf(pz, w2.w, fmaf(py, w1.w, px*w0.w));
    float4 G = P;
    const float* fr = feat + (size_t)p*64;
#pragma unroll 4
    for (int k = 0; k < 64; k += 4) {
        float4 f = *(const float4*)(fr + k);
#pragma unroll
        for (int kk = 0; kk < 4; kk++) {
            float fv = (&f.x)[kk];
            float4 w = *(const float4*)(s_w + (3+k+kk)*64 + c);
            G.x = fmaf(fv, w.x, G.x);
            G.y = fmaf(fv, w.y, G.y);
            G.z = fmaf(fv, w.z, G.z);
            G.w = fmaf(fv, w.w, G.w);
        }
    }
    *(float4*)(g_G + (size_t)p*64 + c) = G;
    *(float4*)(g_P + (size_t)p*64 + c) = P;
}

// ---------------- launch 2: ball query + fused BN1-stats gather ----------------
__global__ __launch_bounds__(256) void bq_kernel(const float* __restrict__ pos) {
    __shared__ float4 s_pq[Nq];
    __shared__ int    s_idx[8][Kq];
    __shared__ float  s_part[8][128];
    int b = blockIdx.y;
    const float* pb = pos + (size_t)b*Nq*3;
    for (int i = threadIdx.x; i < Nq; i += 256) {
        float x = pb[3*i], y = pb[3*i+1], z = pb[3*i+2];
        s_pq[i] = make_float4(x, y, z, x*x + y*y + z*z);
    }
    __syncthreads();
    int w = threadIdx.x >> 5, lane = threadIdx.x & 31;
    int c4 = (lane & 15) * 4;
    const float* Gb = g_G + (((size_t)b*Nq) << 6);
    float sum[4] = {0.f,0.f,0.f,0.f}, sq[4] = {0.f,0.f,0.f,0.f};
    for (int it = 0; it < 8; it++) {
        int j = blockIdx.x*64 + it*8 + w;
        float4 c = s_pq[j];
        int cnt = 0;
        for (int base = 0; base < Nq; base += 32) {
            float4 q = s_pq[base + lane];
            float d = c.w + q.w - 2.0f*(c.x*q.x + c.y*q.y + c.z*q.z);
            bool v = !(d > RAD2);
            unsigned msk = __ballot_sync(0xffffffffu, v);
            int p = cnt + __popc(msk & ((1u << lane) - 1u));
            if (v && p < Kq) s_idx[w][p] = base + lane;
            cnt += __popc(msk);
            if (cnt >= Kq) break;
        }
        __syncwarp();
        int first = s_idx[w][0];
        int nvalid = cnt < Kq ? cnt : Kq;
        int val = (lane < nvalid) ? s_idx[w][lane] : first;
        g_idx[((size_t)b*Nq + j)*Kq + lane] = val;
        float4 p4 = *(const float4*)(g_P + (((size_t)b*Nq + j) << 6) + c4);
#pragma unroll 4
        for (int i = 0; i < 16; i++) {
            int nbA = __shfl_sync(0xffffffffu, val, 2*i);
            int nbB = __shfl_sync(0xffffffffu, val, 2*i+1);
            int nb = (lane < 16) ? nbA : nbB;
            float4 g4 = *(const float4*)(Gb + ((size_t)nb << 6) + c4);
            float h0 = g4.x - p4.x, h1 = g4.y - p4.y;
            float h2 = g4.z - p4.z, h3 = g4.w - p4.w;
            sum[0] += h0; sum[1] += h1; sum[2] += h2; sum[3] += h3;
            sq[0] = fmaf(h0,h0,sq[0]); sq[1] = fmaf(h1,h1,sq[1]);
            sq[2] = fmaf(h2,h2,sq[2]); sq[3] = fmaf(h3,h3,sq[3]);
        }
        __syncwarp();
    }
#pragma unroll
    for (int j = 0; j < 4; j++) {
        sum[j] += __shfl_xor_sync(0xffffffffu, sum[j], 16);
        sq[j]  += __shfl_xor_sync(0xffffffffu, sq[j],  16);
    }
    if (lane < 16) {
#pragma unroll
        for (int j = 0; j < 4; j++) {
            s_part[w][c4 + j]      = sum[j];
            s_part[w][64 + c4 + j] = sq[j];
        }
    }
    __syncthreads();
    int t = threadIdx.x;
    if (t < 128) {
        float v = 0.f;
#pragma unroll
        for (int w2 = 0; w2 < 8; w2++) v += s_part[w2][t];
        atomicAdd(&g_stats1[t], v);
    }
}

// ---------------- launch 3/5: finalize BN stats -> scale/shift ----------------
__global__ void fin1_kernel(const float* __restrict__ gamma, const float* __restrict__ beta) {
    int c = threadIdx.x;
    float inv = 1.0f / (float)ROWS;
    float mean = g_stats1[c] * inv;
    float var  = g_stats1[C1q + c] * inv - mean*mean;
    float sc   = gamma[c] * rsqrtf(var + EPSq);
    g_sc1[c] = sc;
    g_sc1[C1q + c] = beta[c] - mean*sc;
}
__global__ void fin2_kernel(const float* __restrict__ gamma, const float* __restrict__ beta) {
    int c = threadIdx.x;
    float inv = 1.0f / (float)ROWS;
    float mean = g_stats2[c] * inv;
    float var  = g_stats2[C2q + c] * inv - mean*mean;
    float sc   = gamma[c] * rsqrtf(var + EPSq);
    g_sc2[c] = sc;
    g_sc2[C2q + c] = beta[c] - mean*sc;
}

// ---------------- launch 4: bf16-split mma.sync GEMM2 + stats2 + group max/min ----------------
// 2048 CTAs x 8 groups (2 tiles of M=128/N=128/K=64). 8 warps: warp = (group w&3, n-half w>>2).
// D = Ah*Bh + Ah*Bl + Al*Bh in fp32 acc regs. Epilogue: register butterfly reduce over K=32.
#define SM_AH 0
#define SM_AL 16384
#define SM_BH 32768
#define SM_BL 49152
#define SM_STAT 65536        /* 256 floats */
#define SM_SC   66560        /* 128 floats */
#define GEMM2_SMEM (66560 + 512)   /* 67072 B */

__global__ __launch_bounds__(256, 2) void gemm2_kernel() {
    extern __shared__ char smem[];
    uint32_t sb = smem_u32(smem);
    float* s_stat = (float*)(smem + SM_STAT);
    float* s_sc   = (float*)(smem + SM_SC);
    int t = threadIdx.x, w = t >> 5, L = t & 31;

    {   // copy prebuilt swizzled W2^T bf16 images (16 KB each)
        float4* dh = (float4*)(smem + SM_BH);
        float4* dl = (float4*)(smem + SM_BL);
        const float4* shp = (const float4*)g_Bh;
        const float4* slp = (const float4*)g_Bl;
#pragma unroll
        for (int j = 0; j < 4; j++) {
            dh[t + 256*j] = shp[t + 256*j];
            dl[t + 256*j] = slp[t + 256*j];
        }
    }
    if (t < 128) s_sc[t] = g_sc1[t];
    s_stat[t] = 0.f;

    // per-lane ldmatrix addressing constants (SW128 xor depends only on row%8)
    int g = w & 3, nb = (w >> 2) * 64;
    uint32_t xorv = (uint32_t)((L & 7) * 16);
    uint32_t aoff = (uint32_t)((g*32 + (L & 15))*128 + (L >> 4)*16);   // + i*2048 + ks*32
    int nbase = nb + (L & 7) + ((L & 16) ? 8 : 0);
    uint32_t boff = (uint32_t)(nbase*128 + ((L & 8) ? 16 : 0));        // + p*2048 + ks*32

    for (int T = 0; T < 2; T++) {
        int gbase = blockIdx.x*8 + T*4;
        __syncthreads();                  // prior tile's ldmatrix reads done; smem init ready
        // ---- gather + BN1 + ReLU + bf16 hi/lo split -> swizzled A tiles ----
#pragma unroll
        for (int j = 0; j < 8; j++) {
            int i = t + 256*j;
            int g2 = i >> 9, rr = (i >> 4) & 31, c = (i & 15) * 4;
            int gg = gbase + g2;
            int b = gg >> 11;
            int nbi = g_idx[(size_t)gg*32 + rr];
            float4 g4 = *(const float4*)(g_G + (((size_t)(b << 11) + nbi) << 6) + c);
            float4 p4 = *(const float4*)(g_P + ((size_t)gg << 6) + c);
            float h0 = fmaxf(fmaf(g4.x - p4.x, s_sc[c+0], s_sc[64+c+0]), 0.f);
            float h1 = fmaxf(fmaf(g4.y - p4.y, s_sc[c+1], s_sc[64+c+1]), 0.f);
            float h2 = fmaxf(fmaf(g4.z - p4.z, s_sc[c+2], s_sc[64+c+2]), 0.f);
            float h3 = fmaxf(fmaf(g4.w - p4.w, s_sc[c+3], s_sc[64+c+3]), 0.f);
            __nv_bfloat162 ha, hb, la, lb;
            ha.x = __float2bfloat16(h0); ha.y = __float2bfloat16(h1);
            hb.x = __float2bfloat16(h2); hb.y = __float2bfloat16(h3);
            la.x = __float2bfloat16(h0 - __bfloat162float(ha.x));
            la.y = __float2bfloat16(h1 - __bfloat162float(ha.y));
            lb.x = __float2bfloat16(h2 - __bfloat162float(hb.x));
            lb.y = __float2bfloat16(h3 - __bfloat162float(hb.y));
            int row = g2*32 + rr;
            uint32_t sw = SW128((uint32_t)(row*128 + c*2));
            *(uint2*)(smem + SM_AH + sw) = make_uint2(*(uint32_t*)&ha, *(uint32_t*)&hb);
            *(uint2*)(smem + SM_AL + sw) = make_uint2(*(uint32_t*)&la, *(uint32_t*)&lb);
        }
        __syncthreads();

        // ---- mainloop: 4 k-steps x (A-frags + 4 n-pairs x 12 mma) ----
        float acc[2][8][4];
#pragma unroll
        for (int i = 0; i < 2; i++)
#pragma unroll
            for (int n = 0; n < 8; n++)
#pragma unroll
                for (int q = 0; q < 4; q++) acc[i][n][q] = 0.f;

#pragma unroll
        for (int ks = 0; ks < 4; ks++) {
            uint32_t ah[2][4], al[2][4];
#pragma unroll
            for (int i = 0; i < 2; i++) {
                uint32_t lin = aoff + (uint32_t)(i*2048 + ks*32);
                LDSM4(ah[i], sb + SM_AH + (lin ^ xorv));
                LDSM4(al[i], sb + SM_AL + (lin ^ xorv));
            }
#pragma unroll
            for (int p = 0; p < 4; p++) {
                uint32_t lin = boff + (uint32_t)(p*2048 + ks*32);
                uint32_t bh[4], bl[4];
                LDSM4(bh, sb + SM_BH + (lin ^ xorv));
                LDSM4(bl, sb + SM_BL + (lin ^ xorv));
#pragma unroll
                for (int i = 0; i < 2; i++) {
#pragma unroll
                    for (int q = 0; q < 2; q++) {
                        float* c4p = acc[i][2*p + q];
                        MMA16816(c4p, ah[i], bh[2*q], bh[2*q+1]);
                        MMA16816(c4p, ah[i], bl[2*q], bl[2*q+1]);
                        MMA16816(c4p, al[i], bh[2*q], bh[2*q+1]);
                    }
                }
            }
        }

        // ---- epilogue: per-channel reduce over K=32 rows (fragment + lane butterfly) ----
        int ge = gbase + g;
#pragma unroll
        for (int nt = 0; nt < 8; nt++) {
#pragma unroll
            for (int j = 0; j < 2; j++) {
                float v0 = acc[0][nt][j],   v1 = acc[0][nt][j+2];
                float v2 = acc[1][nt][j],   v3 = acc[1][nt][j+2];
                float mx = fmaxf(fmaxf(v0, v1), fmaxf(v2, v3));
                float mn = fminf(fminf(v0, v1), fminf(v2, v3));
                float s  = (v0 + v1) + (v2 + v3);
                float s2 = fmaf(v0, v0, fmaf(v1, v1, fmaf(v2, v2, v3*v3)));
#pragma unroll
                for (int off = 4; off < 32; off <<= 1) {
                    mx = fmaxf(mx, __shfl_xor_sync(0xffffffffu, mx, off));
                    mn = fminf(mn, __shfl_xor_sync(0xffffffffu, mn, off));
                    s  += __shfl_xor_sync(0xffffffffu, s,  off);
                    s2 += __shfl_xor_sync(0xffffffffu, s2, off);
                }
                if (L < 4) {
                    int ch = nb + nt*8 + 2*L + j;
                    g_gmax[(size_t)ge*C2q + ch] = mx;
                    g_gmin[(size_t)ge*C2q + ch] = mn;
                    atomicAdd(&s_stat[ch], s);
                    atomicAdd(&s_stat[128 + ch], s2);
                }
            }
        }
    }
    __syncthreads();
    atomicAdd(&g_stats2[t], s_stat[t]);    // [0..127]=sum, [128..255]=sumsq
}

// ---------------- launch 6: finalize output (affine + relu on per-group max/min) ----------------
__global__ __launch_bounds__(128) void final_kernel(float* __restrict__ out) {
    int c = threadIdx.x;
    float scale = g_sc2[c];
    float shift = g_sc2[C2q + c];
    for (int g = 0; g < 16; g++) {
        size_t gg = (size_t)blockIdx.x*16 + g;
        float v = (scale >= 0.f) ? g_gmax[gg*C2q + c] : g_gmin[gg*C2q + c];
        out[gg*C2q + c] = fmaxf(fmaf(v, scale, shift), 0.f);
    }
}

extern "C" void kernel_launch(void* const* d_in, const int* in_sizes, int n_in,
                              void* d_out, int out_size) {
    (void)in_sizes; (void)n_in; (void)out_size;
    const float* pos  = (const float*)d_in[0];
    const float* feat = (const float*)d_in[1];
    const float* W1   = (const float*)d_in[2];
    const float* g1   = (const float*)d_in[3];
    const float* b1   = (const float*)d_in[4];
    const float* W2   = (const float*)d_in[5];
    const float* g2   = (const float*)d_in[6];
    const float* b2   = (const float*)d_in[7];
    float* out = (float*)d_out;

    cudaFuncSetAttribute(gemm2_kernel, cudaFuncAttributeMaxDynamicSharedMemorySize, GEMM2_SMEM);

    pw_kernel<<<GROUPS*16/256, 256>>>(pos, feat, W1, W2, out); // 1
    bq_kernel<<<dim3(Nq/64, Bq), 256>>>(pos);                  // 2
    fin1_kernel<<<1, C1q>>>(g1, b1);                           // 3
    gemm2_kernel<<<GROUPS/8, 256, GEMM2_SMEM>>>();             // 4  <- profiled slot
    fin2_kernel<<<1, C2q>>>(g2, b2);                           // 5
    final_kernel<<<GROUPS/16, 128>>>(out + (size_t)Bq*Nq*3);   // 6
}

// round 13
// speedup vs baseline: 3.9911x; 1.1424x over previous
#include <cuda_runtime.h>
#include <cuda_bf16.h>
#include <cstdint>

#define Bq 8
#define Nq 2048
#define Kq 32
#define C1q 64
#define C2q 128
#define GROUPS (Bq*Nq)        /* 16384 */
#define ROWS (GROUPS*Kq)      /* 524288 */
#define RAD2 (0.15f*0.15f)
#define EPSq 1e-5f

typedef unsigned long long u64;

// ---------------- scratch (device globals: allocation-free rule) ----------------
__device__ int      g_idx[GROUPS*Kq];                 // 2 MB
__device__ float    g_G[(size_t)GROUPS*C1q];          // 4 MB
__device__ float    g_P[(size_t)GROUPS*C1q];          // 4 MB
__device__ float    g_gmax[(size_t)GROUPS*C2q];       // 8 MB
__device__ float    g_gmin[(size_t)GROUPS*C2q];       // 8 MB
__device__ uint32_t g_Bh[4096];                       // W2^T bf16-hi, SW128-swizzled image
__device__ uint32_t g_Bl[4096];                       // W2^T bf16-lo
__device__ float    g_stats1[2*C1q];
__device__ float    g_stats2[2*C2q];

// ---------------- helpers ----------------
__device__ __forceinline__ uint32_t smem_u32(const void* p) {
    uint32_t a;
    asm("{ .reg .u64 tmp; cvta.to.shared.u64 tmp, %1; cvt.u32.u64 %0, tmp; }"
        : "=r"(a) : "l"(p));
    return a;
}
__device__ __forceinline__ uint32_t prmt(uint32_t a, uint32_t b, uint32_t c) {
    uint32_t d;
    asm("prmt.b32 %0, %1, %2, %3;" : "=r"(d) : "r"(a), "r"(b), "r"(c));
    return d;
}
#define SW128(off) ((off) ^ (((off) >> 3) & 0x70))

#define CVTBF2(d, hi, lo) \
    asm("cvt.rn.bf16x2.f32 %0, %1, %2;" : "=r"(d) : "f"(hi), "f"(lo))

#define MMA16816(c, a, b0, b1) \
    asm volatile("mma.sync.aligned.m16n8k16.row.col.f32.bf16.bf16.f32 " \
        "{%0,%1,%2,%3}, {%4,%5,%6,%7}, {%8,%9}, {%0,%1,%2,%3};" \
        : "+f"((c)[0]), "+f"((c)[1]), "+f"((c)[2]), "+f"((c)[3]) \
        : "r"((a)[0]), "r"((a)[1]), "r"((a)[2]), "r"((a)[3]), "r"(b0), "r"(b1))

#define LDSM4(r, addr) \
    asm volatile("ldmatrix.sync.aligned.m8n8.x4.shared.b16 {%0,%1,%2,%3}, [%4];" \
        : "=r"((r)[0]), "=r"((r)[1]), "=r"((r)[2]), "=r"((r)[3]) : "r"(addr))

// ---------------- launch 1: per-point transforms + passthrough + W2 images + zero ----------------
__global__ __launch_bounds__(256) void pw_kernel(const float* __restrict__ pos,
                                                 const float* __restrict__ feat,
                                                 const float* __restrict__ W1,
                                                 const float* __restrict__ W2,
                                                 float* __restrict__ out) {
    __shared__ float s_w[67*64];
    int t = threadIdx.x;
    for (int i = t; i < 67*64; i += 256) s_w[i] = W1[i];
    if (blockIdx.x == 0) {                 // zero stats accumulators
        if (t < 128) g_stats1[t] = 0.f;
        g_stats2[t] = 0.f;
    }
    if (blockIdx.x < 192) {                // position passthrough
        int i = blockIdx.x*256 + t;
        out[i] = pos[i];
    }
    if (blockIdx.x < 16) {                 // swizzled bf16 hi/lo images of W2^T [n=128][k=64]
        int idx = blockIdx.x*256 + t;
        int n = idx >> 5, j = idx & 31;
        float w0 = W2[(2*j)*128 + n];
        float w1 = W2[(2*j+1)*128 + n];
        __nv_bfloat162 hi;
        hi.x = __float2bfloat16(w0);
        hi.y = __float2bfloat16(w1);
        __nv_bfloat162 lo;
        lo.x = __float2bfloat16(w0 - __bfloat162float(hi.x));
        lo.y = __float2bfloat16(w1 - __bfloat162float(hi.y));
        uint32_t off = (uint32_t)(n*128 + j*4);
        uint32_t sw = SW128(off) >> 2;
        g_Bh[sw] = *(uint32_t*)&hi;
        g_Bl[sw] = *(uint32_t*)&lo;
    }
    __syncthreads();
    int gi = blockIdx.x*256 + t;
    int p = gi >> 4, c = (gi & 15) * 4;
    const float* pp = pos + (size_t)p*3;
    float px = pp[0], py = pp[1], pz = pp[2];
    float4 w0 = *(const float4*)(s_w + 0*64 + c);
    float4 w1 = *(const float4*)(s_w + 1*64 + c);
    float4 w2 = *(const float4*)(s_w + 2*64 + c);
    float4 P;
    P.x = fmaf(pz, w2.x, fmaf(py, w1.x, px*w0.x));
    P.y = fmaf(pz, w2.y, fmaf(py, w1.y, px*w0.y));
    P.z = fmaf(pz, w2.z, fmaf(py, w1.z, px*w0.z));
    P.w = fmaf(pz, w2.w, fmaf(py, w1.w, px*w0.w));
    float4 G = P;
    const float* fr = feat + (size_t)p*64;
#pragma unroll 4
    for (int k = 0; k < 64; k += 4) {
        float4 f = *(const float4*)(fr + k);
#pragma unroll
        for (int kk = 0; kk < 4; kk++) {
            float fv = (&f.x)[kk];
            float4 w = *(const float4*)(s_w + (3+k+kk)*64 + c);
            G.x = fmaf(fv, w.x, G.x);
            G.y = fmaf(fv, w.y, G.y);
            G.z = fmaf(fv, w.z, G.z);
            G.w = fmaf(fv, w.w, G.w);
        }
    }
    *(float4*)(g_G + (size_t)p*64 + c) = G;
    *(float4*)(g_P + (size_t)p*64 + c) = P;
}

// ---------------- launch 2: ball query + fused BN1-stats gather ----------------
__global__ __launch_bounds__(256) void bq_kernel(const float* __restrict__ pos) {
    __shared__ float4 s_pq[Nq];
    __shared__ int    s_idx[8][Kq];
    __shared__ float  s_part[8][128];
    int b = blockIdx.y;
    const float* pb = pos + (size_t)b*Nq*3;
    for (int i = threadIdx.x; i < Nq; i += 256) {
        float x = pb[3*i], y = pb[3*i+1], z = pb[3*i+2];
        s_pq[i] = make_float4(x, y, z, x*x + y*y + z*z);
    }
    __syncthreads();
    int w = threadIdx.x >> 5, lane = threadIdx.x & 31;
    int c4 = (lane & 15) * 4;
    const float* Gb = g_G + (((size_t)b*Nq) << 6);
    float sum[4] = {0.f,0.f,0.f,0.f}, sq[4] = {0.f,0.f,0.f,0.f};
    for (int it = 0; it < 8; it++) {
        int j = blockIdx.x*64 + it*8 + w;
        float4 c = s_pq[j];
        int cnt = 0;
        for (int base = 0; base < Nq; base += 32) {
            float4 q = s_pq[base + lane];
            float d = c.w + q.w - 2.0f*(c.x*q.x + c.y*q.y + c.z*q.z);
            bool v = !(d > RAD2);
            unsigned msk = __ballot_sync(0xffffffffu, v);
            int p = cnt + __popc(msk & ((1u << lane) - 1u));
            if (v && p < Kq) s_idx[w][p] = base + lane;
            cnt += __popc(msk);
            if (cnt >= Kq) break;
        }
        __syncwarp();
        int first = s_idx[w][0];
        int nvalid = cnt < Kq ? cnt : Kq;
        int val = (lane < nvalid) ? s_idx[w][lane] : first;
        g_idx[((size_t)b*Nq + j)*Kq + lane] = val;
        float4 p4 = *(const float4*)(g_P + (((size_t)b*Nq + j) << 6) + c4);
#pragma unroll 4
        for (int i = 0; i < 16; i++) {
            int nbA = __shfl_sync(0xffffffffu, val, 2*i);
            int nbB = __shfl_sync(0xffffffffu, val, 2*i+1);
            int nb = (lane < 16) ? nbA : nbB;
            float4 g4 = *(const float4*)(Gb + ((size_t)nb << 6) + c4);
            float h0 = g4.x - p4.x, h1 = g4.y - p4.y;
            float h2 = g4.z - p4.z, h3 = g4.w - p4.w;
            sum[0] += h0; sum[1] += h1; sum[2] += h2; sum[3] += h3;
            sq[0] = fmaf(h0,h0,sq[0]); sq[1] = fmaf(h1,h1,sq[1]);
            sq[2] = fmaf(h2,h2,sq[2]); sq[3] = fmaf(h3,h3,sq[3]);
        }
        __syncwarp();
    }
#pragma unroll
    for (int j = 0; j < 4; j++) {
        sum[j] += __shfl_xor_sync(0xffffffffu, sum[j], 16);
        sq[j]  += __shfl_xor_sync(0xffffffffu, sq[j],  16);
    }
    if (lane < 16) {
#pragma unroll
        for (int j = 0; j < 4; j++) {
            s_part[w][c4 + j]      = sum[j];
            s_part[w][64 + c4 + j] = sq[j];
        }
    }
    __syncthreads();
    int t = threadIdx.x;
    if (t < 128) {
        float v = 0.f;
#pragma unroll
        for (int w2 = 0; w2 < 8; w2++) v += s_part[w2][t];
        atomicAdd(&g_stats1[t], v);
    }
}

// ---------------- launch 3: bf16-split mma.sync GEMM2 (fin1 inlined) ----------------
#define SM_AH 0
#define SM_AL 16384
#define SM_BH 32768
#define SM_BL 49152
#define SM_STAT 65536        /* 256 floats */
#define SM_SC   66560        /* 128 floats */
#define GEMM2_SMEM (66560 + 512)   /* 67072 B */

__global__ __launch_bounds__(256, 2) void gemm2_kernel(const float* __restrict__ g1,
                                                       const float* __restrict__ b1) {
    extern __shared__ char smem[];
    uint32_t sb = smem_u32(smem);
    float* s_stat = (float*)(smem + SM_STAT);
    float* s_sc   = (float*)(smem + SM_SC);
    int t = threadIdx.x, w = t >> 5, L = t & 31;

    {   // copy prebuilt swizzled W2^T bf16 images (16 KB each)
        float4* dh = (float4*)(smem + SM_BH);
        float4* dl = (float4*)(smem + SM_BL);
        const float4* shp = (const float4*)g_Bh;
        const float4* slp = (const float4*)g_Bl;
#pragma unroll
        for (int j = 0; j < 4; j++) {
            dh[t + 256*j] = shp[t + 256*j];
            dl[t + 256*j] = slp[t + 256*j];
        }
    }
    if (t < 64) {                          // fin1 inline: BN1 scale/shift from g_stats1
        float inv = 1.0f / (float)ROWS;
        float mean = g_stats1[t] * inv;
        float var  = g_stats1[C1q + t] * inv - mean*mean;
        float sc   = g1[t] * rsqrtf(var + EPSq);
        s_sc[t] = sc;
        s_sc[C1q + t] = b1[t] - mean*sc;
    }
    s_stat[t] = 0.f;

    int g = w & 3, nb = (w >> 2) * 64;
    uint32_t xorv = (uint32_t)((L & 7) * 16);
    uint32_t aoff = (uint32_t)((g*32 + (L & 15))*128 + (L >> 4)*16);
    int nbase = nb + (L & 7) + ((L & 16) ? 8 : 0);
    uint32_t boff = (uint32_t)(nbase*128 + ((L & 8) ? 16 : 0));
    int r = L & 3;
    float2* scr2 = (float2*)(smem + SM_AH + w*2560);   // per-warp [64 ch][4+1 pad] float2

    for (int T = 0; T < 2; T++) {
        int gbase = blockIdx.x*8 + T*4;
        __syncthreads();                  // epilogue scratch reads done; smem init ready
        // ---- gather + BN1 + ReLU + truncation hi/lo split -> swizzled A tiles ----
#pragma unroll
        for (int j = 0; j < 8; j++) {
            int i = t + 256*j;
            int g2 = i >> 9, rr = (i >> 4) & 31, c = (i & 15) * 4;
            int gg = gbase + g2;
            int b = gg >> 11;
            int nbi = g_idx[(size_t)gg*32 + rr];
            float4 g4 = *(const float4*)(g_G + (((size_t)(b << 11) + nbi) << 6) + c);
            float4 p4 = *(const float4*)(g_P + ((size_t)gg << 6) + c);
            float h0 = fmaxf(fmaf(g4.x - p4.x, s_sc[c+0], s_sc[64+c+0]), 0.f);
            float h1 = fmaxf(fmaf(g4.y - p4.y, s_sc[c+1], s_sc[64+c+1]), 0.f);
            float h2 = fmaxf(fmaf(g4.z - p4.z, s_sc[c+2], s_sc[64+c+2]), 0.f);
            float h3 = fmaxf(fmaf(g4.w - p4.w, s_sc[c+3], s_sc[64+c+3]), 0.f);
            uint32_t u0 = __float_as_uint(h0), u1 = __float_as_uint(h1);
            uint32_t u2 = __float_as_uint(h2), u3 = __float_as_uint(h3);
            uint32_t ha = prmt(u0, u1, 0x7632);       // truncated bf16 pair (h>=0)
            uint32_t hb = prmt(u2, u3, 0x7632);
            float l0 = h0 - __uint_as_float(u0 & 0xFFFF0000u);
            float l1 = h1 - __uint_as_float(u1 & 0xFFFF0000u);
            float l2 = h2 - __uint_as_float(u2 & 0xFFFF0000u);
            float l3 = h3 - __uint_as_float(u3 & 0xFFFF0000u);
            uint32_t la, lb;
            CVTBF2(la, l1, l0);
            CVTBF2(lb, l3, l2);
            int row = g2*32 + rr;
            uint32_t sw = SW128((uint32_t)(row*128 + c*2));
            *(uint2*)(smem + SM_AH + sw) = make_uint2(ha, hb);
            *(uint2*)(smem + SM_AL + sw) = make_uint2(la, lb);
        }
        __syncthreads();

        // ---- mainloop ----
        float acc[2][8][4];
#pragma unroll
        for (int i = 0; i < 2; i++)
#pragma unroll
            for (int n = 0; n < 8; n++)
#pragma unroll
                for (int q = 0; q < 4; q++) acc[i][n][q] = 0.f;

#pragma unroll
        for (int ks = 0; ks < 4; ks++) {
            uint32_t ah[2][4], al[2][4];
#pragma unroll
            for (int i = 0; i < 2; i++) {
                uint32_t lin = aoff + (uint32_t)(i*2048 + ks*32);
                LDSM4(ah[i], sb + SM_AH + (lin ^ xorv));
                LDSM4(al[i], sb + SM_AL + (lin ^ xorv));
            }
#pragma unroll
            for (int p = 0; p < 4; p++) {
                uint32_t lin = boff + (uint32_t)(p*2048 + ks*32);
                uint32_t bh[4], bl[4];
                LDSM4(bh, sb + SM_BH + (lin ^ xorv));
                LDSM4(bl, sb + SM_BL + (lin ^ xorv));
#pragma unroll
                for (int i = 0; i < 2; i++) {
#pragma unroll
                    for (int q = 0; q < 2; q++) {
                        float* c4p = acc[i][2*p + q];
                        MMA16816(c4p, ah[i], bh[2*q], bh[2*q+1]);
                        MMA16816(c4p, ah[i], bl[2*q], bl[2*q+1]);
                        MMA16816(c4p, al[i], bh[2*q], bh[2*q+1]);
                    }
                }
            }
        }

        // ---- epilogue: 1 shfl level + per-warp staged smem reduce ----
        __syncthreads();                  // all warps done with A region (scratch aliases it)
        int ge = gbase + g;
        // pass A: max/min
#pragma unroll
        for (int nt = 0; nt < 8; nt++) {
#pragma unroll
            for (int j = 0; j < 2; j++) {
                float v0 = acc[0][nt][j], v1 = acc[0][nt][j+2];
                float v2 = acc[1][nt][j], v3 = acc[1][nt][j+2];
                float mx = fmaxf(fmaxf(v0, v1), fmaxf(v2, v3));
                float mn = fminf(fminf(v0, v1), fminf(v2, v3));
                mx = fmaxf(mx, __shfl_xor_sync(0xffffffffu, mx, 16));
                mn = fminf(mn, __shfl_xor_sync(0xffffffffu, mn, 16));
                if (L < 16) scr2[(nt*8 + 2*r + j)*5 + (L >> 2)] = make_float2(mx, mn);
            }
        }
        __syncwarp();
#pragma unroll
        for (int cp = 0; cp < 2; cp++) {
            int chl = L + cp*32;
            float2 e0 = scr2[chl*5+0], e1 = scr2[chl*5+1];
            float2 e2 = scr2[chl*5+2], e3 = scr2[chl*5+3];
            g_gmax[(size_t)ge*C2q + nb + chl] = fmaxf(fmaxf(e0.x, e1.x), fmaxf(e2.x, e3.x));
            g_gmin[(size_t)ge*C2q + nb + chl] = fminf(fminf(e0.y, e1.y), fminf(e2.y, e3.y));
        }
        __syncwarp();
        // pass B: sum/sumsq
#pragma unroll
        for (int nt = 0; nt < 8; nt++) {
#pragma unroll
            for (int j = 0; j < 2; j++) {
                float v0 = acc[0][nt][j], v1 = acc[0][nt][j+2];
                float v2 = acc[1][nt][j], v3 = acc[1][nt][j+2];
                float s  = (v0 + v1) + (v2 + v3);
                float s2 = fmaf(v0, v0, fmaf(v1, v1, fmaf(v2, v2, v3*v3)));
                s  += __shfl_xor_sync(0xffffffffu, s,  16);
                s2 += __shfl_xor_sync(0xffffffffu, s2, 16);
                if (L < 16) scr2[(nt*8 + 2*r + j)*5 + (L >> 2)] = make_float2(s, s2);
            }
        }
        __syncwarp();
#pragma unroll
        for (int cp = 0; cp < 2; cp++) {
            int chl = L + cp*32;
            float2 e0 = scr2[chl*5+0], e1 = scr2[chl*5+1];
            float2 e2 = scr2[chl*5+2], e3 = scr2[chl*5+3];
            atomicAdd(&s_stat[nb + chl],       (e0.x + e1.x) + (e2.x + e3.x));
            atomicAdd(&s_stat[128 + nb + chl], (e0.y + e1.y) + (e2.y + e3.y));
        }
        // loop-top __syncthreads guards scratch/A reuse by next gather
    }
    __syncthreads();
    atomicAdd(&g_stats2[t], s_stat[t]);    // [0..127]=sum, [128..255]=sumsq
}

// ---------------- launch 4: finalize output (fin2 inlined: affine + relu on max/min) ----------------
__global__ __launch_bounds__(128) void final_kernel(const float* __restrict__ g2,
                                                    const float* __restrict__ b2,
                                                    float* __restrict__ out) {
    int c = threadIdx.x;
    float inv = 1.0f / (float)ROWS;
    float mean = g_stats2[c] * inv;
    float var  = g_stats2[C2q + c] * inv - mean*mean;
    float scale = g2[c] * rsqrtf(var + EPSq);
    float shift = b2[c] - mean*scale;
    for (int g = 0; g < 16; g++) {
        size_t gg = (size_t)blockIdx.x*16 + g;
        float v = (scale >= 0.f) ? g_gmax[gg*C2q + c] : g_gmin[gg*C2q + c];
        out[gg*C2q + c] = fmaxf(fmaf(v, scale, shift), 0.f);
    }
}

extern "C" void kernel_launch(void* const* d_in, const int* in_sizes, int n_in,
                              void* d_out, int out_size) {
    (void)in_sizes; (void)n_in; (void)out_size;
    const float* pos  = (const float*)d_in[0];
    const float* feat = (const float*)d_in[1];
    const float* W1   = (const float*)d_in[2];
    const float* g1   = (const float*)d_in[3];
    const float* b1   = (const float*)d_in[4];
    const float* W2   = (const float*)d_in[5];
    const float* g2   = (const float*)d_in[6];
    const float* b2   = (const float*)d_in[7];
    float* out = (float*)d_out;

    cudaFuncSetAttribute(gemm2_kernel, cudaFuncAttributeMaxDynamicSharedMemorySize, GEMM2_SMEM);

    pw_kernel<<<GROUPS*16/256, 256>>>(pos, feat, W1, W2, out); // 1
    bq_kernel<<<dim3(Nq/64, Bq), 256>>>(pos);                  // 2
    gemm2_kernel<<<GROUPS/8, 256, GEMM2_SMEM>>>(g1, b1);       // 3
    final_kernel<<<GROUPS/16, 128>>>(g2, b2, out + (size_t)Bq*Nq*3); // 4
}

// round 14
// speedup vs baseline: 4.2235x; 1.0582x over previous
#include <cuda_runtime.h>
#include <cuda_bf16.h>
#include <cstdint>

#define Bq 8
#define Nq 2048
#define Kq 32
#define C1q 64
#define C2q 128
#define GROUPS (Bq*Nq)        /* 16384 */
#define ROWS (GROUPS*Kq)      /* 524288 */
#define RAD2 (0.15f*0.15f)
#define EPSq 1e-5f

typedef unsigned long long u64;

// ---------------- scratch (device globals: allocation-free rule) ----------------
__device__ int      g_idx[GROUPS*Kq];                 // 2 MB
__device__ float    g_G[(size_t)GROUPS*C1q];          // 4 MB
__device__ float    g_P[(size_t)GROUPS*C1q];          // 4 MB
__device__ float    g_gmax[(size_t)GROUPS*C2q];       // 8 MB
__device__ float    g_gmin[(size_t)GROUPS*C2q];       // 8 MB
__device__ uint32_t g_Bh[4096];                       // W2^T bf16-hi, SW128-swizzled image
__device__ uint32_t g_Bl[4096];                       // W2^T bf16-lo
__device__ float    g_stats1[2*C1q];
__device__ float    g_stats2[2*C2q];

// ---------------- helpers ----------------
__device__ __forceinline__ uint32_t smem_u32(const void* p) {
    uint32_t a;
    asm("{ .reg .u64 tmp; cvta.to.shared.u64 tmp, %1; cvt.u32.u64 %0, tmp; }"
        : "=r"(a) : "l"(p));
    return a;
}
__device__ __forceinline__ uint32_t prmt(uint32_t a, uint32_t b, uint32_t c) {
    uint32_t d;
    asm("prmt.b32 %0, %1, %2, %3;" : "=r"(d) : "r"(a), "r"(b), "r"(c));
    return d;
}
#define SW128(off) ((off) ^ (((off) >> 3) & 0x70))

#define CVTBF2(d, hi, lo) \
    asm("cvt.rn.bf16x2.f32 %0, %1, %2;" : "=r"(d) : "f"(hi), "f"(lo))

#define MMA16816(c, a, b0, b1) \
    asm volatile("mma.sync.aligned.m16n8k16.row.col.f32.bf16.bf16.f32 " \
        "{%0,%1,%2,%3}, {%4,%5,%6,%7}, {%8,%9}, {%0,%1,%2,%3};" \
        : "+f"((c)[0]), "+f"((c)[1]), "+f"((c)[2]), "+f"((c)[3]) \
        : "r"((a)[0]), "r"((a)[1]), "r"((a)[2]), "r"((a)[3]), "r"(b0), "r"(b1))

#define LDSM4(r, addr) \
    asm volatile("ldmatrix.sync.aligned.m8n8.x4.shared.b16 {%0,%1,%2,%3}, [%4];" \
        : "=r"((r)[0]), "=r"((r)[1]), "=r"((r)[2]), "=r"((r)[3]) : "r"(addr))

// ---------------- launch 1: per-point transforms + passthrough + W2 images + zero ----------------
__global__ __launch_bounds__(256) void pw_kernel(const float* __restrict__ pos,
                                                 const float* __restrict__ feat,
                                                 const float* __restrict__ W1,
                                                 const float* __restrict__ W2,
                                                 float* __restrict__ out) {
    __shared__ float s_w[67*64];
    int t = threadIdx.x;
    for (int i = t; i < 67*64; i += 256) s_w[i] = W1[i];
    if (blockIdx.x == 0) {                 // zero stats accumulators
        if (t < 128) g_stats1[t] = 0.f;
        g_stats2[t] = 0.f;
    }
    if (blockIdx.x < 192) {                // position passthrough
        int i = blockIdx.x*256 + t;
        out[i] = pos[i];
    }
    if (blockIdx.x < 16) {                 // swizzled bf16 hi/lo images of W2^T [n=128][k=64]
        int idx = blockIdx.x*256 + t;
        int n = idx >> 5, j = idx & 31;
        float w0 = W2[(2*j)*128 + n];
        float w1 = W2[(2*j+1)*128 + n];
        __nv_bfloat162 hi;
        hi.x = __float2bfloat16(w0);
        hi.y = __float2bfloat16(w1);
        __nv_bfloat162 lo;
        lo.x = __float2bfloat16(w0 - __bfloat162float(hi.x));
        lo.y = __float2bfloat16(w1 - __bfloat162float(hi.y));
        uint32_t off = (uint32_t)(n*128 + j*4);
        uint32_t sw = SW128(off) >> 2;
        g_Bh[sw] = *(uint32_t*)&hi;
        g_Bl[sw] = *(uint32_t*)&lo;
    }
    __syncthreads();
    int gi = blockIdx.x*256 + t;
    int p = gi >> 4, c = (gi & 15) * 4;
    const float* pp = pos + (size_t)p*3;
    float px = pp[0], py = pp[1], pz = pp[2];
    float4 w0 = *(const float4*)(s_w + 0*64 + c);
    float4 w1 = *(const float4*)(s_w + 1*64 + c);
    float4 w2 = *(const float4*)(s_w + 2*64 + c);
    float4 P;
    P.x = fmaf(pz, w2.x, fmaf(py, w1.x, px*w0.x));
    P.y = fmaf(pz, w2.y, fmaf(py, w1.y, px*w0.y));
    P.z = fmaf(pz, w2.z, fmaf(py, w1.z, px*w0.z));
    P.w = fmaf(pz, w2.w, fmaf(py, w1.w, px*w0.w));
    float4 G = P;
    const float* fr = feat + (size_t)p*64;
#pragma unroll 4
    for (int k = 0; k < 64; k += 4) {
        float4 f = *(const float4*)(fr + k);
#pragma unroll
        for (int kk = 0; kk < 4; kk++) {
            float fv = (&f.x)[kk];
            float4 w = *(const float4*)(s_w + (3+k+kk)*64 + c);
            G.x = fmaf(fv, w.x, G.x);
            G.y = fmaf(fv, w.y, G.y);
            G.z = fmaf(fv, w.z, G.z);
            G.w = fmaf(fv, w.w, G.w);
        }
    }
    *(float4*)(g_G + (size_t)p*64 + c) = G;
    *(float4*)(g_P + (size_t)p*64 + c) = P;
}

// ---------------- launch 2: ball query (ILP-2 scan) + fused BN1-stats gather ----------------
__global__ __launch_bounds__(256) void bq_kernel(const float* __restrict__ pos) {
    __shared__ float4 s_pq[Nq];
    __shared__ int    s_idx[8][Kq];
    __shared__ float  s_part[8][128];
    int b = blockIdx.y;
    const float* pb = pos + (size_t)b*Nq*3;
    for (int i = threadIdx.x; i < Nq; i += 256) {
        float x = pb[3*i], y = pb[3*i+1], z = pb[3*i+2];
        s_pq[i] = make_float4(x, y, z, x*x + y*y + z*z);
    }
    __syncthreads();
    int w = threadIdx.x >> 5, lane = threadIdx.x & 31;
    unsigned lmask = (1u << lane) - 1u;
    int c4 = (lane & 15) * 4;
    const float* Gb = g_G + (((size_t)b*Nq) << 6);
    float sum[4] = {0.f,0.f,0.f,0.f}, sq[4] = {0.f,0.f,0.f,0.f};
    for (int it = 0; it < 8; it++) {
        int j = blockIdx.x*64 + it*8 + w;
        float4 c = s_pq[j];
        int cnt = 0;
        for (int base = 0; base < Nq; base += 64) {
            float4 q0 = s_pq[base + lane];
            float4 q1 = s_pq[base + 32 + lane];
            // identical per-candidate arithmetic to the validated scalar version
            float d0 = c.w + q0.w - 2.0f*(c.x*q0.x + c.y*q0.y + c.z*q0.z);
            float d1 = c.w + q1.w - 2.0f*(c.x*q1.x + c.y*q1.y + c.z*q1.z);
            bool v0 = !(d0 > RAD2);
            bool v1 = !(d1 > RAD2);
            unsigned m0 = __ballot_sync(0xffffffffu, v0);
            int p0 = cnt + __popc(m0 & lmask);
            if (v0 && p0 < Kq) s_idx[w][p0] = base + lane;
            cnt += __popc(m0);
            unsigned m1 = __ballot_sync(0xffffffffu, v1);
            int p1 = cnt + __popc(m1 & lmask);
            if (v1 && p1 < Kq) s_idx[w][p1] = base + 32 + lane;
            cnt += __popc(m1);
            if (cnt >= Kq) break;
        }
        __syncwarp();
        int first = s_idx[w][0];
        int nvalid = cnt < Kq ? cnt : Kq;
        int val = (lane < nvalid) ? s_idx[w][lane] : first;
        g_idx[((size_t)b*Nq + j)*Kq + lane] = val;
        float4 p4 = *(const float4*)(g_P + (((size_t)b*Nq + j) << 6) + c4);
#pragma unroll 4
        for (int i = 0; i < 16; i++) {
            int nbA = __shfl_sync(0xffffffffu, val, 2*i);
            int nbB = __shfl_sync(0xffffffffu, val, 2*i+1);
            int nb = (lane < 16) ? nbA : nbB;
            float4 g4 = *(const float4*)(Gb + ((size_t)nb << 6) + c4);
            float h0 = g4.x - p4.x, h1 = g4.y - p4.y;
            float h2 = g4.z - p4.z, h3 = g4.w - p4.w;
            sum[0] += h0; sum[1] += h1; sum[2] += h2; sum[3] += h3;
            sq[0] = fmaf(h0,h0,sq[0]); sq[1] = fmaf(h1,h1,sq[1]);
            sq[2] = fmaf(h2,h2,sq[2]); sq[3] = fmaf(h3,h3,sq[3]);
        }
        __syncwarp();
    }
#pragma unroll
    for (int j = 0; j < 4; j++) {
        sum[j] += __shfl_xor_sync(0xffffffffu, sum[j], 16);
        sq[j]  += __shfl_xor_sync(0xffffffffu, sq[j],  16);
    }
    if (lane < 16) {
#pragma unroll
        for (int j = 0; j < 4; j++) {
            s_part[w][c4 + j]      = sum[j];
            s_part[w][64 + c4 + j] = sq[j];
        }
    }
    __syncthreads();
    int t = threadIdx.x;
    if (t < 128) {
        float v = 0.f;
#pragma unroll
        for (int w2 = 0; w2 < 8; w2++) v += s_part[w2][t];
        atomicAdd(&g_stats1[t], v);
    }
}

// ---------------- launch 3: bf16-split mma.sync GEMM2 (fin1 inlined, 4 tiles/CTA) ----------------
#define SM_AH 0
#define SM_AL 16384
#define SM_BH 32768
#define SM_BL 49152
#define SM_STAT 65536        /* 256 floats */
#define SM_SC   66560        /* 128 floats */
#define SM_IDX  67072        /* 128 ints: idx stage for next tile */
#define SM_SCR  67584        /* 8 warps x 2560 B epilogue scratch */
#define GEMM2_SMEM (67584 + 20480)   /* 88064 B */

__global__ __launch_bounds__(256, 2) void gemm2_kernel(const float* __restrict__ g1,
                                                       const float* __restrict__ b1) {
    extern __shared__ char smem[];
    uint32_t sb = smem_u32(smem);
    float* s_stat  = (float*)(smem + SM_STAT);
    float* s_sc    = (float*)(smem + SM_SC);
    int*   s_idxst = (int*)(smem + SM_IDX);
    int t = threadIdx.x, w = t >> 5, L = t & 31;

    {   // copy prebuilt swizzled W2^T bf16 images (16 KB each)
        float4* dh = (float4*)(smem + SM_BH);
        float4* dl = (float4*)(smem + SM_BL);
        const float4* shp = (const float4*)g_Bh;
        const float4* slp = (const float4*)g_Bl;
#pragma unroll
        for (int j = 0; j < 4; j++) {
            dh[t + 256*j] = shp[t + 256*j];
            dl[t + 256*j] = slp[t + 256*j];
        }
    }
    if (t < 64) {                          // fin1 inline: BN1 scale/shift from g_stats1
        float inv = 1.0f / (float)ROWS;
        float mean = g_stats1[t] * inv;
        float var  = g_stats1[C1q + t] * inv - mean*mean;
        float sc   = g1[t] * rsqrtf(var + EPSq);
        s_sc[t] = sc;
        s_sc[C1q + t] = b1[t] - mean*sc;
    }
    s_stat[t] = 0.f;
    if (t < 128)                           // stage tile 0 indices
        s_idxst[t] = g_idx[(size_t)(blockIdx.x*16)*32 + t];

    int g = w & 3, nb = (w >> 2) * 64;
    uint32_t xorv = (uint32_t)((L & 7) * 16);
    uint32_t aoff = (uint32_t)((g*32 + (L & 15))*128 + (L >> 4)*16);
    int nbase = nb + (L & 7) + ((L & 16) ? 8 : 0);
    uint32_t boff = (uint32_t)(nbase*128 + ((L & 8) ? 16 : 0));
    int r = L & 3;
    float2* scr2 = (float2*)(smem + SM_SCR + w*2560);   // per-warp [64 ch][4+1 pad] float2

    for (int T = 0; T < 4; T++) {
        int gbase = blockIdx.x*16 + T*4;
        __syncthreads();                  // A free (prior mainloop done); smem init/stage ready
        // ---- gather + BN1 + ReLU + truncation hi/lo split -> swizzled A tiles ----
#pragma unroll
        for (int j = 0; j < 8; j++) {
            int i = t + 256*j;
            int g2 = i >> 9, rr = (i >> 4) & 31, c = (i & 15) * 4;
            int gg = gbase + g2;
            int b = gg >> 11;
            int nbi = s_idxst[g2*32 + rr];
            float4 g4 = *(const float4*)(g_G + (((size_t)(b << 11) + nbi) << 6) + c);
            float4 p4 = *(const float4*)(g_P + ((size_t)gg << 6) + c);
            float h0 = fmaxf(fmaf(g4.x - p4.x, s_sc[c+0], s_sc[64+c+0]), 0.f);
            float h1 = fmaxf(fmaf(g4.y - p4.y, s_sc[c+1], s_sc[64+c+1]), 0.f);
            float h2 = fmaxf(fmaf(g4.z - p4.z, s_sc[c+2], s_sc[64+c+2]), 0.f);
            float h3 = fmaxf(fmaf(g4.w - p4.w, s_sc[c+3], s_sc[64+c+3]), 0.f);
            uint32_t u0 = __float_as_uint(h0), u1 = __float_as_uint(h1);
            uint32_t u2 = __float_as_uint(h2), u3 = __float_as_uint(h3);
            uint32_t ha = prmt(u0, u1, 0x7632);       // truncated bf16 pair (h>=0)
            uint32_t hb = prmt(u2, u3, 0x7632);
            float l0 = h0 - __uint_as_float(u0 & 0xFFFF0000u);
            float l1 = h1 - __uint_as_float(u1 & 0xFFFF0000u);
            float l2 = h2 - __uint_as_float(u2 & 0xFFFF0000u);
            float l3 = h3 - __uint_as_float(u3 & 0xFFFF0000u);
            uint32_t la, lb;
            CVTBF2(la, l1, l0);
            CVTBF2(lb, l3, l2);
            int row = g2*32 + rr;
            uint32_t sw = SW128((uint32_t)(row*128 + c*2));
            *(uint2*)(smem + SM_AH + sw) = make_uint2(ha, hb);
            *(uint2*)(smem + SM_AL + sw) = make_uint2(la, lb);
        }
        __syncthreads();
        if (T < 3 && t < 128)             // stage next tile's indices (hidden under mainloop)
            s_idxst[t] = g_idx[(size_t)(gbase + 4)*32 + t];

        // ---- mainloop ----
        float acc[2][8][4];
#pragma unroll
        for (int i = 0; i < 2; i++)
#pragma unroll
            for (int n = 0; n < 8; n++)
#pragma unroll
                for (int q = 0; q < 4; q++) acc[i][n][q] = 0.f;

#pragma unroll
        for (int ks = 0; ks < 4; ks++) {
            uint32_t ah[2][4], al[2][4];
#pragma unroll
            for (int i = 0; i < 2; i++) {
                uint32_t lin = aoff + (uint32_t)(i*2048 + ks*32);
                LDSM4(ah[i], sb + SM_AH + (lin ^ xorv));
                LDSM4(al[i], sb + SM_AL + (lin ^ xorv));
            }
#pragma unroll
            for (int p = 0; p < 4; p++) {
                uint32_t lin = boff + (uint32_t)(p*2048 + ks*32);
                uint32_t bh[4], bl[4];
                LDSM4(bh, sb + SM_BH + (lin ^ xorv));
                LDSM4(bl, sb + SM_BL + (lin ^ xorv));
#pragma unroll
                for (int i = 0; i < 2; i++) {
#pragma unroll
                    for (int q = 0; q < 2; q++) {
                        float* c4p = acc[i][2*p + q];
                        MMA16816(c4p, ah[i], bh[2*q], bh[2*q+1]);
                        MMA16816(c4p, ah[i], bl[2*q], bl[2*q+1]);
                        MMA16816(c4p, al[i], bh[2*q], bh[2*q+1]);
                    }
                }
            }
        }

        // ---- epilogue: warp-asynchronous (dedicated scratch, no block barrier) ----
        int ge = gbase + g;
        // pass A: max/min
#pragma unroll
        for (int nt = 0; nt < 8; nt++) {
#pragma unroll
            for (int j = 0; j < 2; j++) {
                float v0 = acc[0][nt][j], v1 = acc[0][nt][j+2];
                float v2 = acc[1][nt][j], v3 = acc[1][nt][j+2];
                float mx = fmaxf(fmaxf(v0, v1), fmaxf(v2, v3));
                float mn = fminf(fminf(v0, v1), fminf(v2, v3));
                mx = fmaxf(mx, __shfl_xor_sync(0xffffffffu, mx, 16));
                mn = fminf(mn, __shfl_xor_sync(0xffffffffu, mn, 16));
                if (L < 16) scr2[(nt*8 + 2*r + j)*5 + (L >> 2)] = make_float2(mx, mn);
            }
        }
        __syncwarp();
#pragma unroll
        for (int cp = 0; cp < 2; cp++) {
            int chl = L + cp*32;
            float2 e0 = scr2[chl*5+0], e1 = scr2[chl*5+1];
            float2 e2 = scr2[chl*5+2], e3 = scr2[chl*5+3];
            g_gmax[(size_t)ge*C2q + nb + chl] = fmaxf(fmaxf(e0.x, e1.x), fmaxf(e2.x, e3.x));
            g_gmin[(size_t)ge*C2q + nb + chl] = fminf(fminf(e0.y, e1.y), fminf(e2.y, e3.y));
        }
        __syncwarp();
        // pass B: sum/sumsq
#pragma unroll
        for (int nt = 0; nt < 8; nt++) {
#pragma unroll
            for (int j = 0; j < 2; j++) {
                float v0 = acc[0][nt][j], v1 = acc[0][nt][j+2];
                float v2 = acc[1][nt][j], v3 = acc[1][nt][j+2];
                float s  = (v0 + v1) + (v2 + v3);
                float s2 = fmaf(v0, v0, fmaf(v1, v1, fmaf(v2, v2, v3*v3)));
                s  += __shfl_xor_sync(0xffffffffu, s,  16);
                s2 += __shfl_xor_sync(0xffffffffu, s2, 16);
                if (L < 16) scr2[(nt*8 + 2*r + j)*5 + (L >> 2)] = make_float2(s, s2);
            }
        }
        __syncwarp();
#pragma unroll
        for (int cp = 0; cp < 2; cp++) {
            int chl = L + cp*32;
            float2 e0 = scr2[chl*5+0], e1 = scr2[chl*5+1];
            float2 e2 = scr2[chl*5+2], e3 = scr2[chl*5+3];
            atomicAdd(&s_stat[nb + chl],       (e0.x + e1.x) + (e2.x + e3.x));
            atomicAdd(&s_stat[128 + nb + chl], (e0.y + e1.y) + (e2.y + e3.y));
        }
        // loop-top __syncthreads guards A reuse by next gather
    }
    __syncthreads();
    atomicAdd(&g_stats2[t], s_stat[t]);    // [0..127]=sum, [128..255]=sumsq
}

// ---------------- launch 4: finalize output (fin2 inlined; halved read traffic) ----------------
__global__ __launch_bounds__(128) void final_kernel(const float* __restrict__ g2,
                                                    const float* __restrict__ b2,
                                                    float* __restrict__ out) {
    int c = threadIdx.x;
    float inv = 1.0f / (float)ROWS;
    float mean = g_stats2[c] * inv;
    float var  = g_stats2[C2q + c] * inv - mean*mean;
    float scale = g2[c] * rsqrtf(var + EPSq);
    float shift = b2[c] - mean*scale;
    const float* basep = (scale >= 0.f) ? g_gmax : g_gmin;   // per-channel source select
    for (int g = 0; g < 16; g++) {
        size_t gg = (size_t)blockIdx.x*16 + g;
        out[gg*C2q + c] = fmaxf(fmaf(basep[gg*C2q + c], scale, shift), 0.f);
    }
}

extern "C" void kernel_launch(void* const* d_in, const int* in_sizes, int n_in,
                              void* d_out, int out_size) {
    (void)in_sizes; (void)n_in; (void)out_size;
    const float* pos  = (const float*)d_in[0];
    const float* feat = (const float*)d_in[1];
    const float* W1   = (const float*)d_in[2];
    const float* g1   = (const float*)d_in[3];
    const float* b1   = (const float*)d_in[4];
    const float* W2   = (const float*)d_in[5];
    const float* g2   = (const float*)d_in[6];
    const float* b2   = (const float*)d_in[7];
    float* out = (float*)d_out;

    cudaFuncSetAttribute(gemm2_kernel, cudaFuncAttributeMaxDynamicSharedMemorySize, GEMM2_SMEM);

    pw_kernel<<<GROUPS*16/256, 256>>>(pos, feat, W1, W2, out); // 1
    bq_kernel<<<dim3(Nq/64, Bq), 256>>>(pos);                  // 2
    gemm2_kernel<<<GROUPS/16, 256, GEMM2_SMEM>>>(g1, b1);      // 3
    final_kernel<<<GROUPS/16, 128>>>(g2, b2, out + (size_t)Bq*Nq*3); // 4
}